// round 13
// baseline (speedup 1.0000x reference)
#include <cuda_runtime.h>
#include <cuda_fp16.h>
#include <math.h>
#include <stdint.h>

// Problem constants (fixed shapes for this problem)
#define NN    20000
#define EE    640000
#define ETOT0 (EE + NN)
#define TXT   768
#define MELK  6400
#define HID   128

typedef unsigned long long ull;

// ---------------- scratch (static device globals; no allocation) -------------
__device__ float    g_melf[NN * HID];     // relu(mel @ mel_W + b)
__device__ float    g_x0  [NN * HID];     // elu(concat @ concat_W + b)
__device__ __half   g_h1h [NN * 256];     // x0 @ g1_W  (fp16 storage)
__device__ float    g_x1  [NN * 256];     // GAT1 output (after elu)
__device__ uint32_t g_Wh  [HID * MELK / 2];        // mel_W^T as f16x2 [128][6400]
__device__ uint32_t g_Whc [HID * (TXT + HID) / 2]; // concat_W^T as f16x2 [128][896]
__device__ float    g_as1 [NN * 2];
__device__ float    g_ad1 [NN * 2];
__device__ float    g_h2  [NN * 4];
__device__ float    g_as2 [NN];
__device__ float    g_ad2 [NN];
__device__ int      g_deg [NN];
__device__ int      g_rowptr[NN + 1];
__device__ int      g_cursor[NN];
__device__ int      g_csr[ETOT0];

__device__ __forceinline__ float eluf(float x) { return x > 0.f ? x : expm1f(x); }
__device__ __forceinline__ float lrelu(float x) { return x > 0.f ? x : 0.2f * x; }

// ---- packed f32x2 helpers ------------------------------------------------------
__device__ __forceinline__ ull bcast2(float x) {
    ull r; unsigned u = __float_as_uint(x);
    asm("mov.b64 %0, {%1, %1};" : "=l"(r) : "r"(u));
    return r;
}
__device__ __forceinline__ void fma2(ull& d, ull a, ull b) {
    asm("fma.rn.f32x2 %0, %1, %2, %0;" : "+l"(d) : "l"(a), "l"(b));
}
__device__ __forceinline__ float2 unpack2(ull v) {
    unsigned lo, hi;
    asm("mov.b64 {%0, %1}, %2;" : "=r"(lo), "=r"(hi) : "l"(v));
    float2 f; f.x = __uint_as_float(lo); f.y = __uint_as_float(hi);
    return f;
}

// ---- mma.sync / cp.async helpers ------------------------------------------------
__device__ __forceinline__ uint32_t smem_u32(const void* p) {
    uint32_t a;
    asm("{ .reg .u64 t; cvta.to.shared.u64 t, %1; cvt.u32.u64 %0, t; }"
        : "=r"(a) : "l"(p));
    return a;
}
__device__ __forceinline__ void cp16(uint32_t dst, const void* src) {
    asm volatile("cp.async.cg.shared.global [%0], [%1], 16;"
                 :: "r"(dst), "l"(src) : "memory");
}
__device__ __forceinline__ void mma16(float* c, const uint32_t* a, const uint32_t* b) {
    asm volatile(
        "mma.sync.aligned.m16n8k16.row.col.f32.f16.f16.f32 "
        "{%0,%1,%2,%3}, {%4,%5,%6,%7}, {%8,%9}, {%0,%1,%2,%3};"
        : "+f"(c[0]), "+f"(c[1]), "+f"(c[2]), "+f"(c[3])
        : "r"(a[0]), "r"(a[1]), "r"(a[2]), "r"(a[3]), "r"(b[0]), "r"(b[1]));
}
// pack (lo, hi) floats -> f16x2 word (lo in low half)
__device__ __forceinline__ uint32_t f16x2(float lo, float hi) {
    uint32_t r;
    asm("cvt.rn.f16x2.f32 %0, %1, %2;" : "=r"(r) : "f"(hi), "f"(lo));
    return r;
}

// ---------------- W prep: transpose + fp16 pack -----------------------------------
// W[K][128] f32 -> Wh[n][K] f16 (packed as f16x2 words, k contiguous per n-row)
__global__ void wprep_h(const float* __restrict__ W, uint32_t* __restrict__ Wh, int K)
{
    int i = blockIdx.x * 256 + threadIdx.x;
    const int kw = K / 2;
    if (i >= HID * kw) return;
    int n = i / kw, kp = i - n * kw;
    float w0 = W[(size_t)(2 * kp) * HID + n];
    float w1 = W[(size_t)(2 * kp + 1) * HID + n];
    Wh[i] = f16x2(w0, w1);
}

// ---------------- fp16 mma GEMM v3: A direct-from-GMEM, W-only smem ----------------
// C[M,128] = act(A[M,K] @ W + bias); A = logical concat A1|A2 at ksplit (mult of 32).
// CTA: 64x128 tile, 256 thr (8 warps, 4m x 2n of 16x64 warp tiles), K chunks of 32.
// A fragments: LDG.64 f32 pairs straight to registers (sector-perfect), converted
// in regs (prefetch distance 1). W: 4-stage cp.async ring, ONE barrier per chunk.
#define WSTG   10240                               // bytes per W stage (128 rows x 80B)
#define HSMEM  (4 * WSTG)                          // 40960 bytes

__global__ __launch_bounds__(256, 3) void mmagemm_h(
    const float* __restrict__ A1, int lda1, int ksplit,
    const float* __restrict__ A2, int lda2,
    const uint32_t* __restrict__ Wh,
    const float* __restrict__ bias,
    float* __restrict__ C, int ldc,
    int M, int K, int act)
{
    extern __shared__ char smem[];
    const uint32_t sb = smem_u32(smem);
    const int tid  = threadIdx.x;
    const int lane = tid & 31, wid = tid >> 5;
    const int g    = lane >> 2, t = lane & 3;
    const int wm   = wid & 3, wn = wid >> 2;       // 4m x 2n warp grid
    const int mbase = blockIdx.x * 64;
    const int nch   = K >> 5;

    // W cp.async mapping: row = tid>>1 (0..127), seg = tid&1, 2x16B per thread
    const int wrow = tid >> 1;
    const int wseg = tid & 1;

    // A rows this lane owns (clamped; padded rows discarded at store)
    int ra = mbase + wm * 16 + g;  if (ra > M - 1) ra = M - 1;
    int rb = ra + 8;               if (rb > M - 1) rb = M - 1;

    float acc[8][4];
#pragma unroll
    for (int j = 0; j < 8; j++)
#pragma unroll
        for (int q = 0; q < 4; q++) acc[j][q] = 0.f;

    auto issueW = [&](int c) {
        const uint32_t bw = sb + (uint32_t)(c & 3) * WSTG;
        const uint32_t* srcW = Wh + (size_t)wrow * (K >> 1) + c * 16 + wseg * 8;
        cp16(bw + wrow * 80 + wseg * 32, srcW);
        cp16(bw + wrow * 80 + wseg * 32 + 16, srcW + 4);
        asm volatile("cp.async.commit_group;" ::: "memory");
    };

    // A prefetch: 8 float2 (rows ra/rb at k-offsets k0+2t+{0,8,16,24})
    float2 va[4][2];
    auto loadA = [&](int c) {
        const int k0 = c * 32;
        const float* pa;
        const float* pb;
        if (k0 < ksplit) {
            pa = A1 + (size_t)ra * lda1 + k0 + 2 * t;
            pb = A1 + (size_t)rb * lda1 + k0 + 2 * t;
        } else {
            pa = A2 + (size_t)ra * lda2 + (k0 - ksplit) + 2 * t;
            pb = A2 + (size_t)rb * lda2 + (k0 - ksplit) + 2 * t;
        }
#pragma unroll
        for (int ki = 0; ki < 4; ki++) {
            va[ki][0] = *(const float2*)(pa + ki * 8);
            va[ki][1] = *(const float2*)(pb + ki * 8);
        }
    };

    issueW(0);
    if (nch > 1) issueW(1);
    if (nch > 2) issueW(2);
    loadA(0);

    const int brow0 = wn * 64 + g;

    for (int c = 0; c < nch; c++) {
        // convert prefetched A to fragment words before regs are reused
        uint32_t ah[8];   // [s*4 + idx]: idx 0=rowA,k ; 1=rowB,k ; 2=rowA,k+8 ; 3=rowB,k+8
#pragma unroll
        for (int ki = 0; ki < 4; ki++) {
            ah[(ki >> 1) * 4 + (ki & 1) * 2 + 0] = f16x2(va[ki][0].x, va[ki][0].y);
            ah[(ki >> 1) * 4 + (ki & 1) * 2 + 1] = f16x2(va[ki][1].x, va[ki][1].y);
        }
        if (c + 1 < nch) loadA(c + 1);     // LDGs in flight behind compute

        // drain W ring: need group c complete
        const int rem = nch - 1 - c;
        if (rem >= 2)      asm volatile("cp.async.wait_group 2;" ::: "memory");
        else if (rem == 1) asm volatile("cp.async.wait_group 1;" ::: "memory");
        else               asm volatile("cp.async.wait_group 0;" ::: "memory");
        __syncthreads();
        if (c + 3 < nch) issueW(c + 3);    // stage (c+3)&3 == (c-1)&3, consumed last iter

        const uint32_t* Bh = (const uint32_t*)(smem + (c & 3) * WSTG);
#pragma unroll
        for (int s = 0; s < 2; s++) {
            const int kc = 8 * s + t;
            uint32_t b[8][2];
#pragma unroll
            for (int nt = 0; nt < 8; nt++) {
                const int rn = brow0 + nt * 8;
                b[nt][0] = Bh[rn * 20 + kc];
                b[nt][1] = Bh[rn * 20 + kc + 4];
            }
#pragma unroll
            for (int nt = 0; nt < 8; nt++)
                mma16(acc[nt], ah + s * 4, b[nt]);
        }
    }

    // ---- epilogue: bias + act, direct store ----
#pragma unroll
    for (int nt = 0; nt < 8; nt++) {
        const int row = mbase + wm * 16 + g;
        const int col = wn * 64 + nt * 8 + 2 * t;
        float b0 = bias[col], b1 = bias[col + 1];
        float v0 = acc[nt][0] + b0, v1 = acc[nt][1] + b1;
        float v2 = acc[nt][2] + b0, v3 = acc[nt][3] + b1;
        if (act == 1) {
            v0 = fmaxf(v0, 0.f); v1 = fmaxf(v1, 0.f);
            v2 = fmaxf(v2, 0.f); v3 = fmaxf(v3, 0.f);
        } else {
            v0 = eluf(v0); v1 = eluf(v1); v2 = eluf(v2); v3 = eluf(v3);
        }
        if (row < M)     *(float2*)(C + (size_t)row * ldc + col)       = make_float2(v0, v1);
        if (row + 8 < M) *(float2*)(C + (size_t)(row + 8) * ldc + col) = make_float2(v2, v3);
    }
}

// ---------------- GEMM v2 (exact fp32 accum, f32x2) — used for g1 --------------
// out_half: pack result to __half (C reinterpreted as half*, ldc in halves)
#define BM 64
#define BN 128
#define BK 16
#define ASTRIDE 68

__global__ __launch_bounds__(128, 3) void gemm2_kernel(
    const float* __restrict__ A1, int lda1, int ksplit,
    const float* __restrict__ A2, int lda2,
    const float* __restrict__ W, int ldw,
    const float* __restrict__ bias,
    float* __restrict__ C, int ldc,
    int M, int klen, int act, int out_half)
{
    __shared__ float As[BK][ASTRIDE];
    __shared__ float Bs[BK][BN];
    const int tid    = threadIdx.x;
    const int brow   = blockIdx.x * BM;
    const int colOff = blockIdx.y * BN;

    const int tr = tid >> 4;
    const int tc = tid & 15;

    ull acc[8][4];
#pragma unroll
    for (int i = 0; i < 8; i++)
#pragma unroll
        for (int j = 0; j < 4; j++) acc[i][j] = 0ULL;

    const int ar0 = tid >> 2;
    const int ac4 = (tid & 3) * 4;
    const int bq  = (tid & 31) * 4;
    const int br0 = tid >> 5;

    for (int k0 = 0; k0 < klen; k0 += BK) {
#pragma unroll
        for (int h = 0; h < 2; h++) {
            const int row = ar0 + h * 32;
            const int gr  = brow + row;
            const int gk  = k0 + ac4;
            float4 v = make_float4(0.f, 0.f, 0.f, 0.f);
            if (gr < M) {
                const float* p = (gk < ksplit)
                    ? (A1 + (size_t)gr * lda1 + gk)
                    : (A2 + (size_t)gr * lda2 + (gk - ksplit));
                v = *(const float4*)p;
            }
            As[ac4 + 0][row] = v.x;
            As[ac4 + 1][row] = v.y;
            As[ac4 + 2][row] = v.z;
            As[ac4 + 3][row] = v.w;
        }
#pragma unroll
        for (int j = 0; j < 4; j++) {
            const int row = br0 + j * 4;
            const float4 v = *(const float4*)(W + (size_t)(k0 + row) * ldw
                                              + colOff + bq);
            *(float4*)&Bs[row][bq] = v;
        }
        __syncthreads();

#pragma unroll
        for (int kk = 0; kk < BK; kk++) {
            float a[8];
            *(float4*)(a)     = *(const float4*)&As[kk][tr * 8];
            *(float4*)(a + 4) = *(const float4*)&As[kk][tr * 8 + 4];
            ulonglong2 bA = *(const ulonglong2*)&Bs[kk][tc * 4];
            ulonglong2 bB = *(const ulonglong2*)&Bs[kk][64 + tc * 4];
#pragma unroll
            for (int i = 0; i < 8; i++) {
                ull av = bcast2(a[i]);
                fma2(acc[i][0], av, bA.x);
                fma2(acc[i][1], av, bA.y);
                fma2(acc[i][2], av, bB.x);
                fma2(acc[i][3], av, bB.y);
            }
        }
        __syncthreads();
    }

#pragma unroll
    for (int i = 0; i < 8; i++) {
        const int gr = brow + tr * 8 + i;
        if (gr >= M) continue;
        float2 p0 = unpack2(acc[i][0]), p1 = unpack2(acc[i][1]);
        float2 p2 = unpack2(acc[i][2]), p3 = unpack2(acc[i][3]);
        float4 v0 = make_float4(p0.x, p0.y, p1.x, p1.y);
        float4 v1 = make_float4(p2.x, p2.y, p3.x, p3.y);
        const int c0 = colOff + tc * 4;
        const int c1 = colOff + 64 + tc * 4;
        if (bias) {
            v0.x += bias[c0]; v0.y += bias[c0 + 1]; v0.z += bias[c0 + 2]; v0.w += bias[c0 + 3];
            v1.x += bias[c1]; v1.y += bias[c1 + 1]; v1.z += bias[c1 + 2]; v1.w += bias[c1 + 3];
        }
        if (act == 1) {
            v0.x = fmaxf(v0.x, 0.f); v0.y = fmaxf(v0.y, 0.f); v0.z = fmaxf(v0.z, 0.f); v0.w = fmaxf(v0.w, 0.f);
            v1.x = fmaxf(v1.x, 0.f); v1.y = fmaxf(v1.y, 0.f); v1.z = fmaxf(v1.z, 0.f); v1.w = fmaxf(v1.w, 0.f);
        } else if (act == 2) {
            v0.x = eluf(v0.x); v0.y = eluf(v0.y); v0.z = eluf(v0.z); v0.w = eluf(v0.w);
            v1.x = eluf(v1.x); v1.y = eluf(v1.y); v1.z = eluf(v1.z); v1.w = eluf(v1.w);
        }
        if (out_half) {
            __half* dst = (__half*)C + (size_t)gr * ldc;
            uint2 h0, h1;
            h0.x = f16x2(v0.x, v0.y); h0.y = f16x2(v0.z, v0.w);
            h1.x = f16x2(v1.x, v1.y); h1.y = f16x2(v1.z, v1.w);
            *(uint2*)(dst + c0) = h0;
            *(uint2*)(dst + c1) = h1;
        } else {
            float* dst = C + (size_t)gr * ldc;
            *(float4*)(dst + c0) = v0;
            *(float4*)(dst + c1) = v1;
        }
    }
}

// ---------------- CSR build ---------------------------------------------------
__global__ void init_deg_kernel(int n)
{
    int i = blockIdx.x * blockDim.x + threadIdx.x;
    if (i < n) g_deg[i] = 0;
}

__global__ void hist_kernel(const int* __restrict__ ei, int E, int Etot)
{
    int e = blockIdx.x * blockDim.x + threadIdx.x;
    if (e >= Etot) return;
    int dst = (e < E) ? ei[E + e] : (e - E);
    atomicAdd(&g_deg[dst], 1);
}

__global__ __launch_bounds__(1024) void scan_kernel(int n)
{
    __shared__ int sb[1024];
    const int tid = threadIdx.x;
    const int CH  = (NN + 1023) / 1024;   // 20
    int local[CH];
    int base = tid * CH;
    int sum = 0;
#pragma unroll
    for (int j = 0; j < CH; j++) {
        int idx = base + j;
        int v = (idx < n) ? g_deg[idx] : 0;
        local[j] = v;
        sum += v;
    }
    sb[tid] = sum;
    __syncthreads();
    for (int off = 1; off < 1024; off <<= 1) {
        int v = (tid >= off) ? sb[tid - off] : 0;
        __syncthreads();
        sb[tid] += v;
        __syncthreads();
    }
    int run = sb[tid] - sum;
#pragma unroll
    for (int j = 0; j < CH; j++) {
        int idx = base + j;
        if (idx < n) {
            g_rowptr[idx] = run;
            g_cursor[idx] = run;
            run += local[j];
        }
    }
    if (tid == 1023) g_rowptr[n] = sb[1023];
}

__global__ void scatter_kernel(const int* __restrict__ ei, int E, int Etot)
{
    int e = blockIdx.x * blockDim.x + threadIdx.x;
    if (e >= Etot) return;
    int src, dst;
    if (e < E) { src = ei[e]; dst = ei[E + e]; }
    else       { src = e - E; dst = e - E; }
    int pos = atomicAdd(&g_cursor[dst], 1);
    g_csr[pos] = src;
}

// ---------------- GAT1 attention coefficients (h1 in fp16) --------------------
__global__ __launch_bounds__(256) void att1_kernel(
    const float* __restrict__ g1_as, const float* __restrict__ g1_ad, int n)
{
    int p = blockIdx.x * 8 + (threadIdx.x >> 5);
    int lane = threadIdx.x & 31;
    if (p >= n * 2) return;
    int node = p >> 1, h = p & 1;
    uint2 r = *(const uint2*)(g_h1h + (size_t)node * 256 + h * 128 + lane * 4);
    float2 f0 = __half22float2(*(__half2*)&r.x);
    float2 f1 = __half22float2(*(__half2*)&r.y);
    float4 as = *(const float4*)(g1_as + h * 128 + lane * 4);
    float4 ad = *(const float4*)(g1_ad + h * 128 + lane * 4);
    float vs = f0.x * as.x + f0.y * as.y + f1.x * as.z + f1.y * as.w;
    float vd = f0.x * ad.x + f0.y * ad.y + f1.x * ad.z + f1.y * ad.w;
#pragma unroll
    for (int o = 16; o; o >>= 1) {
        vs += __shfl_xor_sync(0xffffffffu, vs, o);
        vd += __shfl_xor_sync(0xffffffffu, vd, o);
    }
    if (lane == 0) { g_as1[p] = vs; g_ad1[p] = vd; }
}

// ---------------- GAT1 aggregate (atomic-free via CSR, fp16 values) ------------
__global__ __launch_bounds__(256) void gat1_kernel(const float* __restrict__ g1_b, int n)
{
    int p = blockIdx.x * 8 + (threadIdx.x >> 5);
    int lane = threadIdx.x & 31;
    if (p >= n * 2) return;
    int node = p >> 1, h = p & 1;
    int beg = g_rowptr[node], end = g_rowptr[node + 1];
    float adv = g_ad1[node * 2 + h];

    float m = -1e30f;
    for (int i = beg + lane; i < end; i += 32) {
        int s = g_csr[i];
        m = fmaxf(m, lrelu(g_as1[s * 2 + h] + adv));
    }
#pragma unroll
    for (int o = 16; o; o >>= 1) m = fmaxf(m, __shfl_xor_sync(0xffffffffu, m, o));

    float ssum = 0.f, ax = 0.f, ay = 0.f, az = 0.f, aw = 0.f;
    const __half* hb = g_h1h + h * 128 + lane * 4;
    for (int i = beg; i < end; ++i) {
        int s = g_csr[i];                                // broadcast load
        float w = expf(lrelu(g_as1[s * 2 + h] + adv) - m);
        ssum += w;
        uint2 r = *(const uint2*)(hb + (size_t)s * 256);
        float2 f0 = __half22float2(*(__half2*)&r.x);
        float2 f1 = __half22float2(*(__half2*)&r.y);
        ax = fmaf(w, f0.x, ax); ay = fmaf(w, f0.y, ay);
        az = fmaf(w, f1.x, az); aw = fmaf(w, f1.y, aw);
    }
    float inv = 1.f / (ssum + 1e-16f);
    int col = h * 128 + lane * 4;
    float4 o;
    o.x = eluf(ax * inv + g1_b[col + 0]);
    o.y = eluf(ay * inv + g1_b[col + 1]);
    o.z = eluf(az * inv + g1_b[col + 2]);
    o.w = eluf(aw * inv + g1_b[col + 3]);
    *(float4*)(g_x1 + (size_t)node * 256 + col) = o;
}

// ---------------- GAT2 projection + attention coefficients --------------------
__global__ __launch_bounds__(256) void h2_kernel(
    const float* __restrict__ g2_W, const float* __restrict__ g2_as,
    const float* __restrict__ g2_ad, int n)
{
    __shared__ float4 sW[256];
    __shared__ float4 s_as, s_ad;
    const int tid = threadIdx.x;
    sW[tid] = *(const float4*)(g2_W + tid * 4);
    if (tid == 0) { s_as = *(const float4*)g2_as; s_ad = *(const float4*)g2_ad; }
    __syncthreads();
    int node = blockIdx.x * 8 + (tid >> 5);
    int lane = tid & 31;
    if (node >= n) return;
    float a0 = 0.f, a1 = 0.f, a2 = 0.f, a3 = 0.f;
    const float* xr = g_x1 + (size_t)node * 256;
    for (int k = lane; k < 256; k += 32) {
        float x = xr[k];
        float4 w = sW[k];
        a0 = fmaf(x, w.x, a0); a1 = fmaf(x, w.y, a1);
        a2 = fmaf(x, w.z, a2); a3 = fmaf(x, w.w, a3);
    }
#pragma unroll
    for (int o = 16; o; o >>= 1) {
        a0 += __shfl_xor_sync(0xffffffffu, a0, o);
        a1 += __shfl_xor_sync(0xffffffffu, a1, o);
        a2 += __shfl_xor_sync(0xffffffffu, a2, o);
        a3 += __shfl_xor_sync(0xffffffffu, a3, o);
    }
    if (lane == 0) {
        *(float4*)(g_h2 + (size_t)node * 4) = make_float4(a0, a1, a2, a3);
        g_as2[node] = a0 * s_as.x + a1 * s_as.y + a2 * s_as.z + a3 * s_as.w;
        g_ad2[node] = a0 * s_ad.x + a1 * s_ad.y + a2 * s_ad.z + a3 * s_ad.w;
    }
}

// ---------------- GAT2 aggregate -> final output ------------------------------
__global__ __launch_bounds__(256) void gat2_kernel(
    const float* __restrict__ g2_b, float* __restrict__ out, int n)
{
    int node = blockIdx.x * 8 + (threadIdx.x >> 5);
    int lane = threadIdx.x & 31;
    if (node >= n) return;
    int beg = g_rowptr[node], end = g_rowptr[node + 1];
    float adv = g_ad2[node];

    float m = -1e30f;
    for (int i = beg + lane; i < end; i += 32) {
        int s = g_csr[i];
        m = fmaxf(m, lrelu(g_as2[s] + adv));
    }
#pragma unroll
    for (int o = 16; o; o >>= 1) m = fmaxf(m, __shfl_xor_sync(0xffffffffu, m, o));

    float ssum = 0.f, a0 = 0.f, a1 = 0.f, a2 = 0.f, a3 = 0.f;
    for (int i = beg + lane; i < end; i += 32) {
        int s = g_csr[i];
        float w = expf(lrelu(g_as2[s] + adv) - m);
        ssum += w;
        float4 hv = *(const float4*)(g_h2 + (size_t)s * 4);
        a0 = fmaf(w, hv.x, a0); a1 = fmaf(w, hv.y, a1);
        a2 = fmaf(w, hv.z, a2); a3 = fmaf(w, hv.w, a3);
    }
#pragma unroll
    for (int o = 16; o; o >>= 1) {
        ssum += __shfl_xor_sync(0xffffffffu, ssum, o);
        a0 += __shfl_xor_sync(0xffffffffu, a0, o);
        a1 += __shfl_xor_sync(0xffffffffu, a1, o);
        a2 += __shfl_xor_sync(0xffffffffu, a2, o);
        a3 += __shfl_xor_sync(0xffffffffu, a3, o);
    }
    if (lane == 0) {
        float inv = 1.f / (ssum + 1e-16f);
        float4 o4 = make_float4(a0 * inv + g2_b[0], a1 * inv + g2_b[1],
                                a2 * inv + g2_b[2], a3 * inv + g2_b[3]);
        *(float4*)(out + (size_t)node * 4) = o4;
    }
}

// ---------------- launch -------------------------------------------------------
extern "C" void kernel_launch(void* const* d_in, const int* in_sizes, int n_in,
                              void* d_out, int out_size)
{
    (void)n_in; (void)out_size;
    const float* text     = (const float*)d_in[0];
    const float* mel      = (const float*)d_in[1];
    const int*   ei       = (const int*)  d_in[2];
    const float* mel_W    = (const float*)d_in[3];
    const float* mel_b    = (const float*)d_in[4];
    const float* concat_W = (const float*)d_in[5];
    const float* concat_b = (const float*)d_in[6];
    const float* g1_W     = (const float*)d_in[7];
    const float* g1_as    = (const float*)d_in[8];
    const float* g1_ad    = (const float*)d_in[9];
    const float* g1_b     = (const float*)d_in[10];
    const float* g2_W     = (const float*)d_in[11];
    const float* g2_as    = (const float*)d_in[12];
    const float* g2_ad    = (const float*)d_in[13];
    const float* g2_b     = (const float*)d_in[14];
    float* out = (float*)d_out;

    const int n    = in_sizes[0] / TXT;       // 20000
    const int E    = in_sizes[2] / 2;         // 640000
    const int Etot = E + n;                   // 660000

    float *p_melf, *p_x0;
    __half* p_h1h;
    uint32_t *p_Wh, *p_Whc;
    cudaGetSymbolAddress((void**)&p_melf, g_melf);
    cudaGetSymbolAddress((void**)&p_x0,   g_x0);
    cudaGetSymbolAddress((void**)&p_h1h,  g_h1h);
    cudaGetSymbolAddress((void**)&p_Wh,   g_Wh);
    cudaGetSymbolAddress((void**)&p_Whc,  g_Whc);

    cudaFuncSetAttribute(mmagemm_h,
                         cudaFuncAttributeMaxDynamicSharedMemorySize, HSMEM);

    // side stream + events for CSR overlap (created once; reused in capture)
    static cudaStream_t s_side = nullptr;
    static cudaEvent_t  ev_fork = nullptr, ev_join = nullptr;
    if (!s_side) {
        cudaStreamCreateWithFlags(&s_side, cudaStreamNonBlocking);
        cudaEventCreateWithFlags(&ev_fork, cudaEventDisableTiming);
        cudaEventCreateWithFlags(&ev_join, cudaEventDisableTiming);
    }

    const int tiles64 = (n + 63) / 64;        // 313
    const int mblocks = (n + BM - 1) / BM;    // 313

    // main #1: W prep for mel
    wprep_h<<<(HID * MELK / 2 + 255) / 256, 256>>>(mel_W, p_Wh, MELK);

    // fork side stream: CSR build runs concurrently with the GEMM pipeline
    cudaEventRecord(ev_fork, 0);
    cudaStreamWaitEvent(s_side, ev_fork, 0);
    init_deg_kernel<<<(n + 255) / 256, 256, 0, s_side>>>(n);
    hist_kernel<<<(Etot + 255) / 256, 256, 0, s_side>>>(ei, E, Etot);

    // mel_feat = relu(mel @ mel_W + mel_b), fp16 mma.sync v3
    mmagemm_h<<<tiles64, 256, HSMEM>>>(
        mel, MELK, MELK, mel, MELK, p_Wh, mel_b, p_melf, HID, n, MELK, 1);

    scan_kernel<<<1, 1024, 0, s_side>>>(n);
    scatter_kernel<<<(Etot + 255) / 256, 256, 0, s_side>>>(ei, E, Etot);
    cudaEventRecord(ev_join, s_side);

    // x0 = elu([text | mel_feat] @ concat_W + concat_b): fp16 mma.sync v3
    wprep_h<<<(HID * (TXT + HID) / 2 + 255) / 256, 256>>>(concat_W, p_Whc, TXT + HID);
    mmagemm_h<<<tiles64, 256, HSMEM>>>(
        text, TXT, TXT, p_melf, HID, p_Whc, concat_b, p_x0, HID, n, TXT + HID, 2);

    // h1 = x0 @ g1_W (fp32 accum, fp16 storage)
    gemm2_kernel<<<dim3(mblocks, 2), 128>>>(p_x0, HID, HID, p_x0, HID,
                                            g1_W, 256, nullptr,
                                            (float*)p_h1h, 256, n, HID, 0, 1);

    att1_kernel<<<(2 * n + 7) / 8, 256>>>(g1_as, g1_ad, n);

    // join: gat1 needs the CSR
    cudaStreamWaitEvent(0, ev_join, 0);
    gat1_kernel<<<(2 * n + 7) / 8, 256>>>(g1_b, n);
    h2_kernel<<<(n + 7) / 8, 256>>>(g2_W, g2_as, g2_ad, n);
    gat2_kernel<<<(n + 7) / 8, 256>>>(g2_b, out, n);
}

// round 14
// speedup vs baseline: 1.2484x; 1.2484x over previous
#include <cuda_runtime.h>
#include <cuda_fp16.h>
#include <math.h>
#include <stdint.h>

// Problem constants (fixed shapes for this problem)
#define NN    20000
#define EE    640000
#define ETOT0 (EE + NN)
#define TXT   768
#define MELK  6400
#define HID   128

typedef unsigned long long ull;

// ---------------- scratch (static device globals; no allocation) -------------
__device__ float    g_melf[NN * HID];     // relu(mel @ mel_W + b)
__device__ float    g_x0  [NN * HID];     // elu(concat @ concat_W + b)
__device__ float    g_part[4 * NN * HID]; // K-split GEMM partials (40MB)
__device__ __half   g_h1h [NN * 256];     // x0 @ g1_W  (fp16 storage)
__device__ float    g_x1  [NN * 256];     // GAT1 output (after elu)
__device__ uint32_t g_Wh  [HID * MELK / 2];        // mel_W^T as f16x2 [128][6400]
__device__ uint32_t g_Whc [HID * (TXT + HID) / 2]; // concat_W^T as f16x2 [128][896]
__device__ float    g_as1 [NN * 2];
__device__ float    g_ad1 [NN * 2];
__device__ float    g_h2  [NN * 4];
__device__ float    g_as2 [NN];
__device__ float    g_ad2 [NN];
__device__ int      g_deg [NN];
__device__ int      g_rowptr[NN + 1];
__device__ int      g_cursor[NN];
__device__ int      g_csr[ETOT0];

__device__ __forceinline__ float eluf(float x) { return x > 0.f ? x : expm1f(x); }
__device__ __forceinline__ float lrelu(float x) { return x > 0.f ? x : 0.2f * x; }

// ---- packed f32x2 helpers ------------------------------------------------------
__device__ __forceinline__ ull bcast2(float x) {
    ull r; unsigned u = __float_as_uint(x);
    asm("mov.b64 %0, {%1, %1};" : "=l"(r) : "r"(u));
    return r;
}
__device__ __forceinline__ void fma2(ull& d, ull a, ull b) {
    asm("fma.rn.f32x2 %0, %1, %2, %0;" : "+l"(d) : "l"(a), "l"(b));
}
__device__ __forceinline__ float2 unpack2(ull v) {
    unsigned lo, hi;
    asm("mov.b64 {%0, %1}, %2;" : "=r"(lo), "=r"(hi) : "l"(v));
    float2 f; f.x = __uint_as_float(lo); f.y = __uint_as_float(hi);
    return f;
}

// ---- mma.sync / cp.async helpers ------------------------------------------------
__device__ __forceinline__ uint32_t smem_u32(const void* p) {
    uint32_t a;
    asm("{ .reg .u64 t; cvta.to.shared.u64 t, %1; cvt.u32.u64 %0, t; }"
        : "=r"(a) : "l"(p));
    return a;
}
__device__ __forceinline__ void cp16(uint32_t dst, const void* src) {
    asm volatile("cp.async.cg.shared.global [%0], [%1], 16;"
                 :: "r"(dst), "l"(src) : "memory");
}
__device__ __forceinline__ void mma16(float* c, const uint32_t* a, const uint32_t* b) {
    asm volatile(
        "mma.sync.aligned.m16n8k16.row.col.f32.f16.f16.f32 "
        "{%0,%1,%2,%3}, {%4,%5,%6,%7}, {%8,%9}, {%0,%1,%2,%3};"
        : "+f"(c[0]), "+f"(c[1]), "+f"(c[2]), "+f"(c[3])
        : "r"(a[0]), "r"(a[1]), "r"(a[2]), "r"(a[3]), "r"(b[0]), "r"(b[1]));
}
// pack (lo, hi) floats -> f16x2 word (lo in low half)
__device__ __forceinline__ uint32_t f16x2(float lo, float hi) {
    uint32_t r;
    asm("cvt.rn.f16x2.f32 %0, %1, %2;" : "=r"(r) : "f"(hi), "f"(lo));
    return r;
}

// ---------------- W prep: transpose + fp16 pack -----------------------------------
// W[K][128] f32 -> Wh[n][K] f16 (packed as f16x2 words, k contiguous per n-row)
__global__ void wprep_h(const float* __restrict__ W, uint32_t* __restrict__ Wh, int K)
{
    int i = blockIdx.x * 256 + threadIdx.x;
    const int kw = K / 2;
    if (i >= HID * kw) return;
    int n = i / kw, kp = i - n * kw;
    float w0 = W[(size_t)(2 * kp) * HID + n];
    float w1 = W[(size_t)(2 * kp + 1) * HID + n];
    Wh[i] = f16x2(w0, w1);
}

// ---------------- fp16 mma GEMM (R12 structure + grid.z K-split) -------------------
// Per split: partial[M,128] = A[M, koff:koff+klen] @ W-chunk. If Part==null (z==1),
// writes act(acc + bias) directly to C. A = logical concat A1|A2 at ksplit.
// CTA: 64x128 tile, 256 thr (8 warps, 4m x 2n of 16x64 warp tiles), K chunks of 32.
#define ASTG32   (64 * 36)                         // floats per f32 A stage (9216B)
#define OFF_BUFA (3 * ASTG32 * 4)                  // 27648
#define OFF_BUFW (OFF_BUFA + 2 * 5120)             // 37888
#define HSMEM    (OFF_BUFW + 3 * 10240)            // 68608 bytes -> 3 CTAs/SM

__global__ __launch_bounds__(256, 3) void mmagemm_h(
    const float* __restrict__ A1, int lda1, int ksplit,
    const float* __restrict__ A2, int lda2,
    const uint32_t* __restrict__ Wh,
    const float* __restrict__ bias,
    float* __restrict__ C, int ldc,
    float* __restrict__ Part,
    int M, int Ktot, int klen, int act)
{
    extern __shared__ char smem[];
    const uint32_t sb = smem_u32(smem);
    const int tid  = threadIdx.x;
    const int lane = tid & 31, wid = tid >> 5;
    const int g    = lane >> 2, t = lane & 3;
    const int wm   = wid & 3, wn = wid >> 2;       // 4m x 2n warp grid
    const int mbase = blockIdx.x * 64;
    const int split = blockIdx.z;
    const int koff  = split * klen;
    const int nch   = klen >> 5;

    // cp.async A mapping: rows crow, crow+32 (16B at ccol)
    const int crow = tid >> 3;
    const int ccol = (tid & 7) * 4;
    // cp.async W mapping: row = tid>>1, seg = tid&1 (32B each)
    const int wrow = tid >> 1;
    const int wseg = tid & 1;
    // convert mapping: row = tid>>2 (0..63), 8 floats at (tid&3)*8
    const int vrow = tid >> 2;
    const int vcol = (tid & 3) * 8;

    float acc[8][4];
#pragma unroll
    for (int j = 0; j < 8; j++)
#pragma unroll
        for (int q = 0; q < 4; q++) acc[j][q] = 0.f;

    auto issue = [&](int c) {
        // A f32 -> stage c%3
        const uint32_t ba = sb + (uint32_t)(c % 3) * (ASTG32 * 4);
        const int k0 = koff + c * 32;
#pragma unroll
        for (int j = 0; j < 2; j++) {
            const int row = crow + j * 32;
            int gr = mbase + row; if (gr > M - 1) gr = M - 1;
            const int gk = k0 + ccol;
            const float* src = (gk < ksplit)
                ? (A1 + (size_t)gr * lda1 + gk)
                : (A2 + (size_t)gr * lda2 + (gk - ksplit));
            cp16(ba + (uint32_t)(row * 36 + ccol) * 4, src);
        }
        // W f16 -> bufW c%3 (64B data per row, 80B row stride)
        const uint32_t bw = sb + OFF_BUFW + (uint32_t)(c % 3) * 10240;
        const uint32_t* srcW = Wh + (size_t)wrow * (Ktot >> 1) + (k0 >> 1) + wseg * 8;
        cp16(bw + wrow * 80 + wseg * 32, srcW);
        cp16(bw + wrow * 80 + wseg * 32 + 16, srcW + 4);
        asm volatile("cp.async.commit_group;" ::: "memory");
    };

    issue(0);
    if (nch > 1) issue(1);

    const int arow0 = wm * 16 + g;
    const int brow0 = wn * 64 + g;

    for (int c = 0; c < nch; c++) {
        if (c + 1 < nch) asm volatile("cp.async.wait_group 1;" ::: "memory");
        else             asm volatile("cp.async.wait_group 0;" ::: "memory");
        __syncthreads();

        // convert A f32 stage(c%3) -> fp16 bufA(c%2): 8 floats per thread
        {
            const float* st32 = (const float*)(smem) + (c % 3) * ASTG32;
            char* ba = smem + OFF_BUFA + (c % 2) * 5120;
#pragma unroll
            for (int q = 0; q < 2; q++) {
                float4 v = *(const float4*)(st32 + vrow * 36 + vcol + q * 4);
                uint2 h;
                h.x = f16x2(v.x, v.y);
                h.y = f16x2(v.z, v.w);
                *(uint2*)(ba + vrow * 80 + vcol * 2 + q * 8) = h;
            }
        }
        __syncthreads();
        if (c + 2 < nch) issue(c + 2);

        const uint32_t* Ah = (const uint32_t*)(smem + OFF_BUFA + (c % 2) * 5120);
        const uint32_t* Bh = (const uint32_t*)(smem + OFF_BUFW + (c % 3) * 10240);
#pragma unroll
        for (int s = 0; s < 2; s++) {
            const int kc = 8 * s + t;
            uint32_t a[4], b[8][2];
            a[0] = Ah[arow0 * 20 + kc];
            a[1] = Ah[(arow0 + 8) * 20 + kc];
            a[2] = Ah[arow0 * 20 + kc + 4];
            a[3] = Ah[(arow0 + 8) * 20 + kc + 4];
#pragma unroll
            for (int nt = 0; nt < 8; nt++) {
                const int rn = brow0 + nt * 8;
                b[nt][0] = Bh[rn * 20 + kc];
                b[nt][1] = Bh[rn * 20 + kc + 4];
            }
#pragma unroll
            for (int nt = 0; nt < 8; nt++)
                mma16(acc[nt], a, b[nt]);
        }
    }

    // ---- epilogue ----
    const int row = mbase + wm * 16 + g;
#pragma unroll
    for (int nt = 0; nt < 8; nt++) {
        const int col = wn * 64 + nt * 8 + 2 * t;
        if (Part) {
            float* dst = Part + ((size_t)split * M + row) * 128 + col;
            if (row < M)     *(float2*)(dst)       = make_float2(acc[nt][0], acc[nt][1]);
            if (row + 8 < M) *(float2*)(dst + 8 * 128) = make_float2(acc[nt][2], acc[nt][3]);
        } else {
            float b0 = bias[col], b1 = bias[col + 1];
            float v0 = acc[nt][0] + b0, v1 = acc[nt][1] + b1;
            float v2 = acc[nt][2] + b0, v3 = acc[nt][3] + b1;
            if (act == 1) {
                v0 = fmaxf(v0, 0.f); v1 = fmaxf(v1, 0.f);
                v2 = fmaxf(v2, 0.f); v3 = fmaxf(v3, 0.f);
            } else {
                v0 = eluf(v0); v1 = eluf(v1); v2 = eluf(v2); v3 = eluf(v3);
            }
            if (row < M)     *(float2*)(C + (size_t)row * ldc + col)       = make_float2(v0, v1);
            if (row + 8 < M) *(float2*)(C + (size_t)(row + 8) * ldc + col) = make_float2(v2, v3);
        }
    }
}

// ---------------- combine K-split partials: dst = act(sum + bias) -------------
__global__ void combine_kernel(int nsplit, int total4, const float* __restrict__ bias,
                               float* __restrict__ dst, int act, int stride4)
{
    int i = blockIdx.x * blockDim.x + threadIdx.x;
    if (i >= total4) return;
    const float4* p = (const float4*)g_part;
    float4 v = p[i];
    for (int s = 1; s < nsplit; s++) {
        float4 w = p[i + s * stride4];
        v.x += w.x; v.y += w.y; v.z += w.z; v.w += w.w;
    }
    const int col = (i * 4) & 127;   // ldc = 128
    v.x += bias[col]; v.y += bias[col + 1]; v.z += bias[col + 2]; v.w += bias[col + 3];
    if (act == 1) {
        v.x = fmaxf(v.x, 0.f); v.y = fmaxf(v.y, 0.f); v.z = fmaxf(v.z, 0.f); v.w = fmaxf(v.w, 0.f);
    } else {
        v.x = eluf(v.x); v.y = eluf(v.y); v.z = eluf(v.z); v.w = eluf(v.w);
    }
    ((float4*)dst)[i] = v;
}

// ---------------- GEMM v2 (exact fp32 accum, f32x2) — used for g1 --------------
#define BM 64
#define BN 128
#define BK 16
#define ASTRIDE 68

__global__ __launch_bounds__(128, 3) void gemm2_kernel(
    const float* __restrict__ A1, int lda1, int ksplit,
    const float* __restrict__ A2, int lda2,
    const float* __restrict__ W, int ldw,
    const float* __restrict__ bias,
    float* __restrict__ C, int ldc,
    int M, int klen, int act, int out_half)
{
    __shared__ float As[BK][ASTRIDE];
    __shared__ float Bs[BK][BN];
    const int tid    = threadIdx.x;
    const int brow   = blockIdx.x * BM;
    const int colOff = blockIdx.y * BN;

    const int tr = tid >> 4;
    const int tc = tid & 15;

    ull acc[8][4];
#pragma unroll
    for (int i = 0; i < 8; i++)
#pragma unroll
        for (int j = 0; j < 4; j++) acc[i][j] = 0ULL;

    const int ar0 = tid >> 2;
    const int ac4 = (tid & 3) * 4;
    const int bq  = (tid & 31) * 4;
    const int br0 = tid >> 5;

    for (int k0 = 0; k0 < klen; k0 += BK) {
#pragma unroll
        for (int h = 0; h < 2; h++) {
            const int row = ar0 + h * 32;
            const int gr  = brow + row;
            const int gk  = k0 + ac4;
            float4 v = make_float4(0.f, 0.f, 0.f, 0.f);
            if (gr < M) {
                const float* p = (gk < ksplit)
                    ? (A1 + (size_t)gr * lda1 + gk)
                    : (A2 + (size_t)gr * lda2 + (gk - ksplit));
                v = *(const float4*)p;
            }
            As[ac4 + 0][row] = v.x;
            As[ac4 + 1][row] = v.y;
            As[ac4 + 2][row] = v.z;
            As[ac4 + 3][row] = v.w;
        }
#pragma unroll
        for (int j = 0; j < 4; j++) {
            const int row = br0 + j * 4;
            const float4 v = *(const float4*)(W + (size_t)(k0 + row) * ldw
                                              + colOff + bq);
            *(float4*)&Bs[row][bq] = v;
        }
        __syncthreads();

#pragma unroll
        for (int kk = 0; kk < BK; kk++) {
            float a[8];
            *(float4*)(a)     = *(const float4*)&As[kk][tr * 8];
            *(float4*)(a + 4) = *(const float4*)&As[kk][tr * 8 + 4];
            ulonglong2 bA = *(const ulonglong2*)&Bs[kk][tc * 4];
            ulonglong2 bB = *(const ulonglong2*)&Bs[kk][64 + tc * 4];
#pragma unroll
            for (int i = 0; i < 8; i++) {
                ull av = bcast2(a[i]);
                fma2(acc[i][0], av, bA.x);
                fma2(acc[i][1], av, bA.y);
                fma2(acc[i][2], av, bB.x);
                fma2(acc[i][3], av, bB.y);
            }
        }
        __syncthreads();
    }

#pragma unroll
    for (int i = 0; i < 8; i++) {
        const int gr = brow + tr * 8 + i;
        if (gr >= M) continue;
        float2 p0 = unpack2(acc[i][0]), p1 = unpack2(acc[i][1]);
        float2 p2 = unpack2(acc[i][2]), p3 = unpack2(acc[i][3]);
        float4 v0 = make_float4(p0.x, p0.y, p1.x, p1.y);
        float4 v1 = make_float4(p2.x, p2.y, p3.x, p3.y);
        const int c0 = colOff + tc * 4;
        const int c1 = colOff + 64 + tc * 4;
        if (bias) {
            v0.x += bias[c0]; v0.y += bias[c0 + 1]; v0.z += bias[c0 + 2]; v0.w += bias[c0 + 3];
            v1.x += bias[c1]; v1.y += bias[c1 + 1]; v1.z += bias[c1 + 2]; v1.w += bias[c1 + 3];
        }
        if (act == 1) {
            v0.x = fmaxf(v0.x, 0.f); v0.y = fmaxf(v0.y, 0.f); v0.z = fmaxf(v0.z, 0.f); v0.w = fmaxf(v0.w, 0.f);
            v1.x = fmaxf(v1.x, 0.f); v1.y = fmaxf(v1.y, 0.f); v1.z = fmaxf(v1.z, 0.f); v1.w = fmaxf(v1.w, 0.f);
        } else if (act == 2) {
            v0.x = eluf(v0.x); v0.y = eluf(v0.y); v0.z = eluf(v0.z); v0.w = eluf(v0.w);
            v1.x = eluf(v1.x); v1.y = eluf(v1.y); v1.z = eluf(v1.z); v1.w = eluf(v1.w);
        }
        if (out_half) {
            __half* dst = (__half*)C + (size_t)gr * ldc;
            uint2 h0, h1;
            h0.x = f16x2(v0.x, v0.y); h0.y = f16x2(v0.z, v0.w);
            h1.x = f16x2(v1.x, v1.y); h1.y = f16x2(v1.z, v1.w);
            *(uint2*)(dst + c0) = h0;
            *(uint2*)(dst + c1) = h1;
        } else {
            float* dst = C + (size_t)gr * ldc;
            *(float4*)(dst + c0) = v0;
            *(float4*)(dst + c1) = v1;
        }
    }
}

// ---------------- CSR build ---------------------------------------------------
__global__ void init_deg_kernel(int n)
{
    int i = blockIdx.x * blockDim.x + threadIdx.x;
    if (i < n) g_deg[i] = 0;
}

__global__ void hist_kernel(const int* __restrict__ ei, int E, int Etot)
{
    int e = blockIdx.x * blockDim.x + threadIdx.x;
    if (e >= Etot) return;
    int dst = (e < E) ? ei[E + e] : (e - E);
    atomicAdd(&g_deg[dst], 1);
}

__global__ __launch_bounds__(1024) void scan_kernel(int n)
{
    __shared__ int sb[1024];
    const int tid = threadIdx.x;
    const int CH  = (NN + 1023) / 1024;   // 20
    int local[CH];
    int base = tid * CH;
    int sum = 0;
#pragma unroll
    for (int j = 0; j < CH; j++) {
        int idx = base + j;
        int v = (idx < n) ? g_deg[idx] : 0;
        local[j] = v;
        sum += v;
    }
    sb[tid] = sum;
    __syncthreads();
    for (int off = 1; off < 1024; off <<= 1) {
        int v = (tid >= off) ? sb[tid - off] : 0;
        __syncthreads();
        sb[tid] += v;
        __syncthreads();
    }
    int run = sb[tid] - sum;
#pragma unroll
    for (int j = 0; j < CH; j++) {
        int idx = base + j;
        if (idx < n) {
            g_rowptr[idx] = run;
            g_cursor[idx] = run;
            run += local[j];
        }
    }
    if (tid == 1023) g_rowptr[n] = sb[1023];
}

__global__ void scatter_kernel(const int* __restrict__ ei, int E, int Etot)
{
    int e = blockIdx.x * blockDim.x + threadIdx.x;
    if (e >= Etot) return;
    int src, dst;
    if (e < E) { src = ei[e]; dst = ei[E + e]; }
    else       { src = e - E; dst = e - E; }
    int pos = atomicAdd(&g_cursor[dst], 1);
    g_csr[pos] = src;
}

// ---------------- GAT1 attention coefficients (h1 in fp16) --------------------
__global__ __launch_bounds__(256) void att1_kernel(
    const float* __restrict__ g1_as, const float* __restrict__ g1_ad, int n)
{
    int p = blockIdx.x * 8 + (threadIdx.x >> 5);
    int lane = threadIdx.x & 31;
    if (p >= n * 2) return;
    int node = p >> 1, h = p & 1;
    uint2 r = *(const uint2*)(g_h1h + (size_t)node * 256 + h * 128 + lane * 4);
    float2 f0 = __half22float2(*(__half2*)&r.x);
    float2 f1 = __half22float2(*(__half2*)&r.y);
    float4 as = *(const float4*)(g1_as + h * 128 + lane * 4);
    float4 ad = *(const float4*)(g1_ad + h * 128 + lane * 4);
    float vs = f0.x * as.x + f0.y * as.y + f1.x * as.z + f1.y * as.w;
    float vd = f0.x * ad.x + f0.y * ad.y + f1.x * ad.z + f1.y * ad.w;
#pragma unroll
    for (int o = 16; o; o >>= 1) {
        vs += __shfl_xor_sync(0xffffffffu, vs, o);
        vd += __shfl_xor_sync(0xffffffffu, vd, o);
    }
    if (lane == 0) { g_as1[p] = vs; g_ad1[p] = vd; }
}

// ---------------- GAT1 aggregate (atomic-free via CSR, fp16 values) ------------
__global__ __launch_bounds__(256) void gat1_kernel(const float* __restrict__ g1_b, int n)
{
    int p = blockIdx.x * 8 + (threadIdx.x >> 5);
    int lane = threadIdx.x & 31;
    if (p >= n * 2) return;
    int node = p >> 1, h = p & 1;
    int beg = g_rowptr[node], end = g_rowptr[node + 1];
    float adv = g_ad1[node * 2 + h];

    float m = -1e30f;
    for (int i = beg + lane; i < end; i += 32) {
        int s = g_csr[i];
        m = fmaxf(m, lrelu(g_as1[s * 2 + h] + adv));
    }
#pragma unroll
    for (int o = 16; o; o >>= 1) m = fmaxf(m, __shfl_xor_sync(0xffffffffu, m, o));

    float ssum = 0.f, ax = 0.f, ay = 0.f, az = 0.f, aw = 0.f;
    const __half* hb = g_h1h + h * 128 + lane * 4;
    for (int i = beg; i < end; ++i) {
        int s = g_csr[i];                                // broadcast load
        float w = expf(lrelu(g_as1[s * 2 + h] + adv) - m);
        ssum += w;
        uint2 r = *(const uint2*)(hb + (size_t)s * 256);
        float2 f0 = __half22float2(*(__half2*)&r.x);
        float2 f1 = __half22float2(*(__half2*)&r.y);
        ax = fmaf(w, f0.x, ax); ay = fmaf(w, f0.y, ay);
        az = fmaf(w, f1.x, az); aw = fmaf(w, f1.y, aw);
    }
    float inv = 1.f / (ssum + 1e-16f);
    int col = h * 128 + lane * 4;
    float4 o;
    o.x = eluf(ax * inv + g1_b[col + 0]);
    o.y = eluf(ay * inv + g1_b[col + 1]);
    o.z = eluf(az * inv + g1_b[col + 2]);
    o.w = eluf(aw * inv + g1_b[col + 3]);
    *(float4*)(g_x1 + (size_t)node * 256 + col) = o;
}

// ---------------- GAT2 projection + attention coefficients --------------------
__global__ __launch_bounds__(256) void h2_kernel(
    const float* __restrict__ g2_W, const float* __restrict__ g2_as,
    const float* __restrict__ g2_ad, int n)
{
    __shared__ float4 sW[256];
    __shared__ float4 s_as, s_ad;
    const int tid = threadIdx.x;
    sW[tid] = *(const float4*)(g2_W + tid * 4);
    if (tid == 0) { s_as = *(const float4*)g2_as; s_ad = *(const float4*)g2_ad; }
    __syncthreads();
    int node = blockIdx.x * 8 + (tid >> 5);
    int lane = tid & 31;
    if (node >= n) return;
    float a0 = 0.f, a1 = 0.f, a2 = 0.f, a3 = 0.f;
    const float* xr = g_x1 + (size_t)node * 256;
    for (int k = lane; k < 256; k += 32) {
        float x = xr[k];
        float4 w = sW[k];
        a0 = fmaf(x, w.x, a0); a1 = fmaf(x, w.y, a1);
        a2 = fmaf(x, w.z, a2); a3 = fmaf(x, w.w, a3);
    }
#pragma unroll
    for (int o = 16; o; o >>= 1) {
        a0 += __shfl_xor_sync(0xffffffffu, a0, o);
        a1 += __shfl_xor_sync(0xffffffffu, a1, o);
        a2 += __shfl_xor_sync(0xffffffffu, a2, o);
        a3 += __shfl_xor_sync(0xffffffffu, a3, o);
    }
    if (lane == 0) {
        *(float4*)(g_h2 + (size_t)node * 4) = make_float4(a0, a1, a2, a3);
        g_as2[node] = a0 * s_as.x + a1 * s_as.y + a2 * s_as.z + a3 * s_as.w;
        g_ad2[node] = a0 * s_ad.x + a1 * s_ad.y + a2 * s_ad.z + a3 * s_ad.w;
    }
}

// ---------------- GAT2 aggregate -> final output ------------------------------
__global__ __launch_bounds__(256) void gat2_kernel(
    const float* __restrict__ g2_b, float* __restrict__ out, int n)
{
    int node = blockIdx.x * 8 + (threadIdx.x >> 5);
    int lane = threadIdx.x & 31;
    if (node >= n) return;
    int beg = g_rowptr[node], end = g_rowptr[node + 1];
    float adv = g_ad2[node];

    float m = -1e30f;
    for (int i = beg + lane; i < end; i += 32) {
        int s = g_csr[i];
        m = fmaxf(m, lrelu(g_as2[s] + adv));
    }
#pragma unroll
    for (int o = 16; o; o >>= 1) m = fmaxf(m, __shfl_xor_sync(0xffffffffu, m, o));

    float ssum = 0.f, a0 = 0.f, a1 = 0.f, a2 = 0.f, a3 = 0.f;
    for (int i = beg + lane; i < end; i += 32) {
        int s = g_csr[i];
        float w = expf(lrelu(g_as2[s] + adv) - m);
        ssum += w;
        float4 hv = *(const float4*)(g_h2 + (size_t)s * 4);
        a0 = fmaf(w, hv.x, a0); a1 = fmaf(w, hv.y, a1);
        a2 = fmaf(w, hv.z, a2); a3 = fmaf(w, hv.w, a3);
    }
#pragma unroll
    for (int o = 16; o; o >>= 1) {
        ssum += __shfl_xor_sync(0xffffffffu, ssum, o);
        a0 += __shfl_xor_sync(0xffffffffu, a0, o);
        a1 += __shfl_xor_sync(0xffffffffu, a1, o);
        a2 += __shfl_xor_sync(0xffffffffu, a2, o);
        a3 += __shfl_xor_sync(0xffffffffu, a3, o);
    }
    if (lane == 0) {
        float inv = 1.f / (ssum + 1e-16f);
        float4 o4 = make_float4(a0 * inv + g2_b[0], a1 * inv + g2_b[1],
                                a2 * inv + g2_b[2], a3 * inv + g2_b[3]);
        *(float4*)(out + (size_t)node * 4) = o4;
    }
}

// ---------------- launch -------------------------------------------------------
extern "C" void kernel_launch(void* const* d_in, const int* in_sizes, int n_in,
                              void* d_out, int out_size)
{
    (void)n_in; (void)out_size;
    const float* text     = (const float*)d_in[0];
    const float* mel      = (const float*)d_in[1];
    const int*   ei       = (const int*)  d_in[2];
    const float* mel_W    = (const float*)d_in[3];
    const float* mel_b    = (const float*)d_in[4];
    const float* concat_W = (const float*)d_in[5];
    const float* concat_b = (const float*)d_in[6];
    const float* g1_W     = (const float*)d_in[7];
    const float* g1_as    = (const float*)d_in[8];
    const float* g1_ad    = (const float*)d_in[9];
    const float* g1_b     = (const float*)d_in[10];
    const float* g2_W     = (const float*)d_in[11];
    const float* g2_as    = (const float*)d_in[12];
    const float* g2_ad    = (const float*)d_in[13];
    const float* g2_b     = (const float*)d_in[14];
    float* out = (float*)d_out;

    const int n    = in_sizes[0] / TXT;       // 20000
    const int E    = in_sizes[2] / 2;         // 640000
    const int Etot = E + n;                   // 660000

    float *p_melf, *p_x0, *p_part;
    __half* p_h1h;
    uint32_t *p_Wh, *p_Whc;
    cudaGetSymbolAddress((void**)&p_melf, g_melf);
    cudaGetSymbolAddress((void**)&p_x0,   g_x0);
    cudaGetSymbolAddress((void**)&p_part, g_part);
    cudaGetSymbolAddress((void**)&p_h1h,  g_h1h);
    cudaGetSymbolAddress((void**)&p_Wh,   g_Wh);
    cudaGetSymbolAddress((void**)&p_Whc,  g_Whc);

    cudaFuncSetAttribute(mmagemm_h,
                         cudaFuncAttributeMaxDynamicSharedMemorySize, HSMEM);

    // side stream + events for CSR overlap (created once; reused in capture)
    static cudaStream_t s_side = nullptr;
    static cudaEvent_t  ev_fork = nullptr, ev_join = nullptr;
    if (!s_side) {
        cudaStreamCreateWithFlags(&s_side, cudaStreamNonBlocking);
        cudaEventCreateWithFlags(&ev_fork, cudaEventDisableTiming);
        cudaEventCreateWithFlags(&ev_join, cudaEventDisableTiming);
    }

    const int tiles64 = (n + 63) / 64;        // 313
    const int mblocks = (n + BM - 1) / BM;    // 313
    const int total4  = n * HID / 4;
    const int stride4 = n * HID / 4;

    // main #1: W prep for mel
    wprep_h<<<(HID * MELK / 2 + 255) / 256, 256>>>(mel_W, p_Wh, MELK);

    // fork side stream: CSR build runs concurrently with the GEMM pipeline
    cudaEventRecord(ev_fork, 0);
    cudaStreamWaitEvent(s_side, ev_fork, 0);
    init_deg_kernel<<<(n + 255) / 256, 256, 0, s_side>>>(n);
    hist_kernel<<<(Etot + 255) / 256, 256, 0, s_side>>>(ei, E, Etot);

    // mel_feat = relu(mel @ mel_W + mel_b): fp16 mma.sync, 4-way K-split
    mmagemm_h<<<dim3(tiles64, 1, 4), 256, HSMEM>>>(
        mel, MELK, MELK, mel, MELK, p_Wh, nullptr,
        nullptr, HID, p_part, n, MELK, MELK / 4, 0);
    combine_kernel<<<(total4 + 255) / 256, 256>>>(4, total4, mel_b, p_melf, 1, stride4);

    scan_kernel<<<1, 1024, 0, s_side>>>(n);
    scatter_kernel<<<(Etot + 255) / 256, 256, 0, s_side>>>(ei, E, Etot);
    cudaEventRecord(ev_join, s_side);

    // x0 = elu([text | mel_feat] @ concat_W + concat_b): fp16 mma.sync, 2-way split
    wprep_h<<<(HID * (TXT + HID) / 2 + 255) / 256, 256>>>(concat_W, p_Whc, TXT + HID);
    mmagemm_h<<<dim3(tiles64, 1, 2), 256, HSMEM>>>(
        text, TXT, TXT, p_melf, HID, p_Whc, nullptr,
        nullptr, HID, p_part, n, TXT + HID, (TXT + HID) / 2, 0);
    combine_kernel<<<(total4 + 255) / 256, 256>>>(2, total4, concat_b, p_x0, 2, stride4);

    // h1 = x0 @ g1_W (fp32 accum, fp16 storage)
    gemm2_kernel<<<dim3(mblocks, 2), 128>>>(p_x0, HID, HID, p_x0, HID,
                                            g1_W, 256, nullptr,
                                            (float*)p_h1h, 256, n, HID, 0, 1);

    att1_kernel<<<(2 * n + 7) / 8, 256>>>(g1_as, g1_ad, n);

    // join: gat1 needs the CSR
    cudaStreamWaitEvent(0, ev_join, 0);
    gat1_kernel<<<(2 * n + 7) / 8, 256>>>(g1_b, n);
    h2_kernel<<<(n + 7) / 8, 256>>>(g2_W, g2_as, g2_ad, n);
    gat2_kernel<<<(n + 7) / 8, 256>>>(g2_b, out, n);
}

// round 15
// speedup vs baseline: 1.3129x; 1.0517x over previous
#include <cuda_runtime.h>
#include <cuda_fp16.h>
#include <math.h>
#include <stdint.h>

// Problem constants (fixed shapes for this problem)
#define NN    20000
#define EE    640000
#define ETOT0 (EE + NN)
#define TXT   768
#define MELK  6400
#define HID   128

typedef unsigned long long ull;

// ---------------- scratch (static device globals; no allocation) -------------
__device__ float    g_melf[NN * HID];     // relu(mel @ mel_W + b)
__device__ float    g_x0  [NN * HID];     // elu(concat @ concat_W + b)
__device__ float    g_part[4 * NN * HID]; // K-split GEMM partials (40MB)
__device__ __half   g_h1h [NN * 256];     // x0 @ g1_W  (fp16 storage)
__device__ float    g_x1  [NN * 256];     // GAT1 output (after elu)
__device__ uint32_t g_Wh  [HID * MELK / 2];        // mel_W^T as f16x2 [128][6400]
__device__ uint32_t g_Whc [HID * (TXT + HID) / 2]; // concat_W^T as f16x2 [128][896]
__device__ float    g_as1 [NN * 2];
__device__ float    g_ad1 [NN * 2];
__device__ float    g_h2  [NN * 4];
__device__ float    g_as2 [NN];
__device__ float    g_ad2 [NN];
__device__ int      g_deg [NN];
__device__ int      g_rowptr[NN + 1];
__device__ int      g_cursor[NN];
__device__ int      g_csr[ETOT0];

__device__ __forceinline__ float eluf(float x) { return x > 0.f ? x : expm1f(x); }
__device__ __forceinline__ float lrelu(float x) { return x > 0.f ? x : 0.2f * x; }

// ---- packed f32x2 helpers ------------------------------------------------------
__device__ __forceinline__ ull bcast2(float x) {
    ull r; unsigned u = __float_as_uint(x);
    asm("mov.b64 %0, {%1, %1};" : "=l"(r) : "r"(u));
    return r;
}
__device__ __forceinline__ void fma2(ull& d, ull a, ull b) {
    asm("fma.rn.f32x2 %0, %1, %2, %0;" : "+l"(d) : "l"(a), "l"(b));
}
__device__ __forceinline__ float2 unpack2(ull v) {
    unsigned lo, hi;
    asm("mov.b64 {%0, %1}, %2;" : "=r"(lo), "=r"(hi) : "l"(v));
    float2 f; f.x = __uint_as_float(lo); f.y = __uint_as_float(hi);
    return f;
}

// ---- mma.sync / cp.async helpers ------------------------------------------------
__device__ __forceinline__ uint32_t smem_u32(const void* p) {
    uint32_t a;
    asm("{ .reg .u64 t; cvta.to.shared.u64 t, %1; cvt.u32.u64 %0, t; }"
        : "=r"(a) : "l"(p));
    return a;
}
__device__ __forceinline__ void cp16(uint32_t dst, const void* src) {
    asm volatile("cp.async.cg.shared.global [%0], [%1], 16;"
                 :: "r"(dst), "l"(src) : "memory");
}
__device__ __forceinline__ void mma16(float* c, const uint32_t* a, const uint32_t* b) {
    asm volatile(
        "mma.sync.aligned.m16n8k16.row.col.f32.f16.f16.f32 "
        "{%0,%1,%2,%3}, {%4,%5,%6,%7}, {%8,%9}, {%0,%1,%2,%3};"
        : "+f"(c[0]), "+f"(c[1]), "+f"(c[2]), "+f"(c[3])
        : "r"(a[0]), "r"(a[1]), "r"(a[2]), "r"(a[3]), "r"(b[0]), "r"(b[1]));
}
// pack (lo, hi) floats -> f16x2 word (lo in low half)
__device__ __forceinline__ uint32_t f16x2(float lo, float hi) {
    uint32_t r;
    asm("cvt.rn.f16x2.f32 %0, %1, %2;" : "=r"(r) : "f"(hi), "f"(lo));
    return r;
}

// ---------------- W prep: transpose + fp16 pack -----------------------------------
// W[K][128] f32 -> Wh[n][K] f16 (packed as f16x2 words, k contiguous per n-row)
__global__ void wprep_h(const float* __restrict__ W, uint32_t* __restrict__ Wh, int K)
{
    int i = blockIdx.x * 256 + threadIdx.x;
    const int kw = K / 2;
    if (i >= HID * kw) return;
    int n = i / kw, kp = i - n * kw;
    float w0 = W[(size_t)(2 * kp) * HID + n];
    float w1 = W[(size_t)(2 * kp + 1) * HID + n];
    Wh[i] = f16x2(w0, w1);
}

// ---------------- fp16 mma GEMM: 128x128 tile + grid.z K-split ---------------------
// Per split: partial[M,128] = A[M, koff:koff+klen] @ W-chunk (raw fp32 partials).
// If Part==null (z==1): writes act(acc + bias) directly to C.
// A = logical concat A1|A2 at ksplit (multiple of 32). CTA: 128x128 tile, 256 thr
// (8 warps, 4m x 2n of 32x64 warp tiles), K chunks of 32. A streamed via cp.async
// f32 (3 stages) -> in-kernel fp16 convert (2 bufs); W cp.async'd as fp16 (3 bufs).
// half tile rows stride 20 words (80B).
#define HSTG_A32  (128 * 36)                       // floats per f32 A stage
#define OFF_BUFA  (3 * HSTG_A32 * 4)               // 55296
#define OFF_BUFW  (OFF_BUFA + 2 * 10240)           // 75776
#define HSMEM     (OFF_BUFW + 3 * 10240)           // 106496 bytes -> 2 CTAs/SM

__global__ __launch_bounds__(256, 2) void mmagemm_h(
    const float* __restrict__ A1, int lda1, int ksplit,
    const float* __restrict__ A2, int lda2,
    const uint32_t* __restrict__ Wh,
    const float* __restrict__ bias,
    float* __restrict__ C, int ldc,
    float* __restrict__ Part,
    int M, int Ktot, int klen, int act)
{
    extern __shared__ char smem[];
    const uint32_t sb = smem_u32(smem);
    const int tid  = threadIdx.x;
    const int lane = tid & 31, wid = tid >> 5;
    const int g    = lane >> 2, t = lane & 3;
    const int wm   = wid & 3, wn = wid >> 2;       // 4m x 2n warp grid
    const int mbase = blockIdx.x * 128;
    const int split = blockIdx.z;
    const int koff  = split * klen;
    const int nch   = klen >> 5;

    // cp.async A mapping: 4 rows (crow+32j), 16B at ccol
    const int crow = tid >> 3;
    const int ccol = (tid & 7) * 4;
    // cp.async W mapping: row = tid>>1, seg = tid&1 (32B each)
    const int wrow = tid >> 1;
    const int wseg = tid & 1;
    // convert mapping: row = tid>>1, seg = tid&1 (16 floats each)
    const int vrow = tid >> 1;
    const int vcol = (tid & 1) * 16;

    float acc[2][8][4];
#pragma unroll
    for (int i = 0; i < 2; i++)
#pragma unroll
        for (int j = 0; j < 8; j++)
#pragma unroll
            for (int q = 0; q < 4; q++) acc[i][j][q] = 0.f;

    auto issue = [&](int c) {
        // A f32 -> stage c%3
        const uint32_t ba = sb + (uint32_t)(c % 3) * (HSTG_A32 * 4);
        const int k0 = koff + c * 32;
#pragma unroll
        for (int j = 0; j < 4; j++) {
            const int row = crow + j * 32;
            int gr = mbase + row; if (gr > M - 1) gr = M - 1;
            const int gk = k0 + ccol;
            const float* src = (gk < ksplit)
                ? (A1 + (size_t)gr * lda1 + gk)
                : (A2 + (size_t)gr * lda2 + (gk - ksplit));
            cp16(ba + (uint32_t)(row * 36 + ccol) * 4, src);
        }
        // W f16 -> bufW c%3 (64B data per row, 80B row stride)
        const uint32_t bw = sb + OFF_BUFW + (uint32_t)(c % 3) * 10240;
        const uint32_t* srcW = Wh + (size_t)wrow * (Ktot >> 1) + (k0 >> 1) + wseg * 8;
        cp16(bw + wrow * 80 + wseg * 32, srcW);
        cp16(bw + wrow * 80 + wseg * 32 + 16, srcW + 4);
        asm volatile("cp.async.commit_group;" ::: "memory");
    };

    issue(0);
    if (nch > 1) issue(1);

    const int arow0 = wm * 32 + g;
    const int brow0 = wn * 64 + g;

    for (int c = 0; c < nch; c++) {
        if (c + 1 < nch) asm volatile("cp.async.wait_group 1;" ::: "memory");
        else             asm volatile("cp.async.wait_group 0;" ::: "memory");
        __syncthreads();

        // convert A f32 stage(c%3) -> fp16 bufA(c%2)
        {
            const float* st32 = (const float*)(smem) + (c % 3) * HSTG_A32;
            char* ba = smem + OFF_BUFA + (c % 2) * 10240;
#pragma unroll
            for (int q = 0; q < 4; q++) {
                float4 v = *(const float4*)(st32 + vrow * 36 + vcol + q * 4);
                uint2 h;
                h.x = f16x2(v.x, v.y);
                h.y = f16x2(v.z, v.w);
                *(uint2*)(ba + vrow * 80 + vcol * 2 + q * 8) = h;
            }
        }
        __syncthreads();
        if (c + 2 < nch) issue(c + 2);

        const uint32_t* Ah = (const uint32_t*)(smem + OFF_BUFA + (c % 2) * 10240);
        const uint32_t* Bh = (const uint32_t*)(smem + OFF_BUFW + (c % 3) * 10240);
#pragma unroll
        for (int s = 0; s < 2; s++) {
            const int kc = 8 * s + t;
            uint32_t a[2][4], b[8][2];
#pragma unroll
            for (int mt = 0; mt < 2; mt++) {
                const int r = arow0 + mt * 16;
                a[mt][0] = Ah[r * 20 + kc];
                a[mt][1] = Ah[(r + 8) * 20 + kc];
                a[mt][2] = Ah[r * 20 + kc + 4];
                a[mt][3] = Ah[(r + 8) * 20 + kc + 4];
            }
#pragma unroll
            for (int nt = 0; nt < 8; nt++) {
                const int rn = brow0 + nt * 8;
                b[nt][0] = Bh[rn * 20 + kc];
                b[nt][1] = Bh[rn * 20 + kc + 4];
            }
#pragma unroll
            for (int mt = 0; mt < 2; mt++)
#pragma unroll
                for (int nt = 0; nt < 8; nt++)
                    mma16(acc[mt][nt], a[mt], b[nt]);
        }
    }

    // ---- epilogue ----
#pragma unroll
    for (int mt = 0; mt < 2; mt++) {
        const int row = mbase + wm * 32 + mt * 16 + g;
#pragma unroll
        for (int nt = 0; nt < 8; nt++) {
            const int col = wn * 64 + nt * 8 + 2 * t;
            if (Part) {
                float* dst = Part + ((size_t)split * M + row) * 128 + col;
                if (row < M)     *(float2*)(dst)           = make_float2(acc[mt][nt][0], acc[mt][nt][1]);
                if (row + 8 < M) *(float2*)(dst + 8 * 128) = make_float2(acc[mt][nt][2], acc[mt][nt][3]);
            } else {
                float b0 = bias[col], b1 = bias[col + 1];
                float v0 = acc[mt][nt][0] + b0, v1 = acc[mt][nt][1] + b1;
                float v2 = acc[mt][nt][2] + b0, v3 = acc[mt][nt][3] + b1;
                if (act == 1) {
                    v0 = fmaxf(v0, 0.f); v1 = fmaxf(v1, 0.f);
                    v2 = fmaxf(v2, 0.f); v3 = fmaxf(v3, 0.f);
                } else {
                    v0 = eluf(v0); v1 = eluf(v1); v2 = eluf(v2); v3 = eluf(v3);
                }
                if (row < M)     *(float2*)(C + (size_t)row * ldc + col)       = make_float2(v0, v1);
                if (row + 8 < M) *(float2*)(C + (size_t)(row + 8) * ldc + col) = make_float2(v2, v3);
            }
        }
    }
}

// ---------------- combine K-split partials: dst = act(sum + bias) -------------
__global__ void combine_kernel(int nsplit, int total4, const float* __restrict__ bias,
                               float* __restrict__ dst, int act, int stride4)
{
    int i = blockIdx.x * blockDim.x + threadIdx.x;
    if (i >= total4) return;
    const float4* p = (const float4*)g_part;
    float4 v = p[i];
    for (int s = 1; s < nsplit; s++) {
        float4 w = p[i + s * stride4];
        v.x += w.x; v.y += w.y; v.z += w.z; v.w += w.w;
    }
    const int col = (i * 4) & 127;   // ldc = 128
    v.x += bias[col]; v.y += bias[col + 1]; v.z += bias[col + 2]; v.w += bias[col + 3];
    if (act == 1) {
        v.x = fmaxf(v.x, 0.f); v.y = fmaxf(v.y, 0.f); v.z = fmaxf(v.z, 0.f); v.w = fmaxf(v.w, 0.f);
    } else {
        v.x = eluf(v.x); v.y = eluf(v.y); v.z = eluf(v.z); v.w = eluf(v.w);
    }
    ((float4*)dst)[i] = v;
}

// ---------------- GEMM v2 (exact fp32 accum, f32x2) — used for g1 --------------
#define BM 64
#define BN 128
#define BK 16
#define ASTRIDE 68

__global__ __launch_bounds__(128, 3) void gemm2_kernel(
    const float* __restrict__ A1, int lda1, int ksplit,
    const float* __restrict__ A2, int lda2,
    const float* __restrict__ W, int ldw,
    const float* __restrict__ bias,
    float* __restrict__ C, int ldc,
    int M, int klen, int act, int out_half)
{
    __shared__ float As[BK][ASTRIDE];
    __shared__ float Bs[BK][BN];
    const int tid    = threadIdx.x;
    const int brow   = blockIdx.x * BM;
    const int colOff = blockIdx.y * BN;

    const int tr = tid >> 4;
    const int tc = tid & 15;

    ull acc[8][4];
#pragma unroll
    for (int i = 0; i < 8; i++)
#pragma unroll
        for (int j = 0; j < 4; j++) acc[i][j] = 0ULL;

    const int ar0 = tid >> 2;
    const int ac4 = (tid & 3) * 4;
    const int bq  = (tid & 31) * 4;
    const int br0 = tid >> 5;

    for (int k0 = 0; k0 < klen; k0 += BK) {
#pragma unroll
        for (int h = 0; h < 2; h++) {
            const int row = ar0 + h * 32;
            const int gr  = brow + row;
            const int gk  = k0 + ac4;
            float4 v = make_float4(0.f, 0.f, 0.f, 0.f);
            if (gr < M) {
                const float* p = (gk < ksplit)
                    ? (A1 + (size_t)gr * lda1 + gk)
                    : (A2 + (size_t)gr * lda2 + (gk - ksplit));
                v = *(const float4*)p;
            }
            As[ac4 + 0][row] = v.x;
            As[ac4 + 1][row] = v.y;
            As[ac4 + 2][row] = v.z;
            As[ac4 + 3][row] = v.w;
        }
#pragma unroll
        for (int j = 0; j < 4; j++) {
            const int row = br0 + j * 4;
            const float4 v = *(const float4*)(W + (size_t)(k0 + row) * ldw
                                              + colOff + bq);
            *(float4*)&Bs[row][bq] = v;
        }
        __syncthreads();

#pragma unroll
        for (int kk = 0; kk < BK; kk++) {
            float a[8];
            *(float4*)(a)     = *(const float4*)&As[kk][tr * 8];
            *(float4*)(a + 4) = *(const float4*)&As[kk][tr * 8 + 4];
            ulonglong2 bA = *(const ulonglong2*)&Bs[kk][tc * 4];
            ulonglong2 bB = *(const ulonglong2*)&Bs[kk][64 + tc * 4];
#pragma unroll
            for (int i = 0; i < 8; i++) {
                ull av = bcast2(a[i]);
                fma2(acc[i][0], av, bA.x);
                fma2(acc[i][1], av, bA.y);
                fma2(acc[i][2], av, bB.x);
                fma2(acc[i][3], av, bB.y);
            }
        }
        __syncthreads();
    }

#pragma unroll
    for (int i = 0; i < 8; i++) {
        const int gr = brow + tr * 8 + i;
        if (gr >= M) continue;
        float2 p0 = unpack2(acc[i][0]), p1 = unpack2(acc[i][1]);
        float2 p2 = unpack2(acc[i][2]), p3 = unpack2(acc[i][3]);
        float4 v0 = make_float4(p0.x, p0.y, p1.x, p1.y);
        float4 v1 = make_float4(p2.x, p2.y, p3.x, p3.y);
        const int c0 = colOff + tc * 4;
        const int c1 = colOff + 64 + tc * 4;
        if (bias) {
            v0.x += bias[c0]; v0.y += bias[c0 + 1]; v0.z += bias[c0 + 2]; v0.w += bias[c0 + 3];
            v1.x += bias[c1]; v1.y += bias[c1 + 1]; v1.z += bias[c1 + 2]; v1.w += bias[c1 + 3];
        }
        if (act == 1) {
            v0.x = fmaxf(v0.x, 0.f); v0.y = fmaxf(v0.y, 0.f); v0.z = fmaxf(v0.z, 0.f); v0.w = fmaxf(v0.w, 0.f);
            v1.x = fmaxf(v1.x, 0.f); v1.y = fmaxf(v1.y, 0.f); v1.z = fmaxf(v1.z, 0.f); v1.w = fmaxf(v1.w, 0.f);
        } else if (act == 2) {
            v0.x = eluf(v0.x); v0.y = eluf(v0.y); v0.z = eluf(v0.z); v0.w = eluf(v0.w);
            v1.x = eluf(v1.x); v1.y = eluf(v1.y); v1.z = eluf(v1.z); v1.w = eluf(v1.w);
        }
        if (out_half) {
            __half* dst = (__half*)C + (size_t)gr * ldc;
            uint2 h0, h1;
            h0.x = f16x2(v0.x, v0.y); h0.y = f16x2(v0.z, v0.w);
            h1.x = f16x2(v1.x, v1.y); h1.y = f16x2(v1.z, v1.w);
            *(uint2*)(dst + c0) = h0;
            *(uint2*)(dst + c1) = h1;
        } else {
            float* dst = C + (size_t)gr * ldc;
            *(float4*)(dst + c0) = v0;
            *(float4*)(dst + c1) = v1;
        }
    }
}

// ---------------- CSR build ---------------------------------------------------
__global__ void init_deg_kernel(int n)
{
    int i = blockIdx.x * blockDim.x + threadIdx.x;
    if (i < n) g_deg[i] = 0;
}

__global__ void hist_kernel(const int* __restrict__ ei, int E, int Etot)
{
    int e = blockIdx.x * blockDim.x + threadIdx.x;
    if (e >= Etot) return;
    int dst = (e < E) ? ei[E + e] : (e - E);
    atomicAdd(&g_deg[dst], 1);
}

__global__ __launch_bounds__(1024) void scan_kernel(int n)
{
    __shared__ int sb[1024];
    const int tid = threadIdx.x;
    const int CH  = (NN + 1023) / 1024;   // 20
    int local[CH];
    int base = tid * CH;
    int sum = 0;
#pragma unroll
    for (int j = 0; j < CH; j++) {
        int idx = base + j;
        int v = (idx < n) ? g_deg[idx] : 0;
        local[j] = v;
        sum += v;
    }
    sb[tid] = sum;
    __syncthreads();
    for (int off = 1; off < 1024; off <<= 1) {
        int v = (tid >= off) ? sb[tid - off] : 0;
        __syncthreads();
        sb[tid] += v;
        __syncthreads();
    }
    int run = sb[tid] - sum;
#pragma unroll
    for (int j = 0; j < CH; j++) {
        int idx = base + j;
        if (idx < n) {
            g_rowptr[idx] = run;
            g_cursor[idx] = run;
            run += local[j];
        }
    }
    if (tid == 1023) g_rowptr[n] = sb[1023];
}

__global__ void scatter_kernel(const int* __restrict__ ei, int E, int Etot)
{
    int e = blockIdx.x * blockDim.x + threadIdx.x;
    if (e >= Etot) return;
    int src, dst;
    if (e < E) { src = ei[e]; dst = ei[E + e]; }
    else       { src = e - E; dst = e - E; }
    int pos = atomicAdd(&g_cursor[dst], 1);
    g_csr[pos] = src;
}

// ---------------- GAT1 attention coefficients (h1 in fp16) --------------------
__global__ __launch_bounds__(256) void att1_kernel(
    const float* __restrict__ g1_as, const float* __restrict__ g1_ad, int n)
{
    int p = blockIdx.x * 8 + (threadIdx.x >> 5);
    int lane = threadIdx.x & 31;
    if (p >= n * 2) return;
    int node = p >> 1, h = p & 1;
    uint2 r = *(const uint2*)(g_h1h + (size_t)node * 256 + h * 128 + lane * 4);
    float2 f0 = __half22float2(*(__half2*)&r.x);
    float2 f1 = __half22float2(*(__half2*)&r.y);
    float4 as = *(const float4*)(g1_as + h * 128 + lane * 4);
    float4 ad = *(const float4*)(g1_ad + h * 128 + lane * 4);
    float vs = f0.x * as.x + f0.y * as.y + f1.x * as.z + f1.y * as.w;
    float vd = f0.x * ad.x + f0.y * ad.y + f1.x * ad.z + f1.y * ad.w;
#pragma unroll
    for (int o = 16; o; o >>= 1) {
        vs += __shfl_xor_sync(0xffffffffu, vs, o);
        vd += __shfl_xor_sync(0xffffffffu, vd, o);
    }
    if (lane == 0) { g_as1[p] = vs; g_ad1[p] = vd; }
}

// ---------------- GAT1 aggregate (atomic-free via CSR, fp16 values) ------------
__global__ __launch_bounds__(256) void gat1_kernel(const float* __restrict__ g1_b, int n)
{
    int p = blockIdx.x * 8 + (threadIdx.x >> 5);
    int lane = threadIdx.x & 31;
    if (p >= n * 2) return;
    int node = p >> 1, h = p & 1;
    int beg = g_rowptr[node], end = g_rowptr[node + 1];
    float adv = g_ad1[node * 2 + h];

    float m = -1e30f;
    for (int i = beg + lane; i < end; i += 32) {
        int s = g_csr[i];
        m = fmaxf(m, lrelu(g_as1[s * 2 + h] + adv));
    }
#pragma unroll
    for (int o = 16; o; o >>= 1) m = fmaxf(m, __shfl_xor_sync(0xffffffffu, m, o));

    float ssum = 0.f, ax = 0.f, ay = 0.f, az = 0.f, aw = 0.f;
    const __half* hb = g_h1h + h * 128 + lane * 4;
    for (int i = beg; i < end; ++i) {
        int s = g_csr[i];                                // broadcast load
        float w = expf(lrelu(g_as1[s * 2 + h] + adv) - m);
        ssum += w;
        uint2 r = *(const uint2*)(hb + (size_t)s * 256);
        float2 f0 = __half22float2(*(__half2*)&r.x);
        float2 f1 = __half22float2(*(__half2*)&r.y);
        ax = fmaf(w, f0.x, ax); ay = fmaf(w, f0.y, ay);
        az = fmaf(w, f1.x, az); aw = fmaf(w, f1.y, aw);
    }
    float inv = 1.f / (ssum + 1e-16f);
    int col = h * 128 + lane * 4;
    float4 o;
    o.x = eluf(ax * inv + g1_b[col + 0]);
    o.y = eluf(ay * inv + g1_b[col + 1]);
    o.z = eluf(az * inv + g1_b[col + 2]);
    o.w = eluf(aw * inv + g1_b[col + 3]);
    *(float4*)(g_x1 + (size_t)node * 256 + col) = o;
}

// ---------------- GAT2 projection + attention coefficients --------------------
__global__ __launch_bounds__(256) void h2_kernel(
    const float* __restrict__ g2_W, const float* __restrict__ g2_as,
    const float* __restrict__ g2_ad, int n)
{
    __shared__ float4 sW[256];
    __shared__ float4 s_as, s_ad;
    const int tid = threadIdx.x;
    sW[tid] = *(const float4*)(g2_W + tid * 4);
    if (tid == 0) { s_as = *(const float4*)g2_as; s_ad = *(const float4*)g2_ad; }
    __syncthreads();
    int node = blockIdx.x * 8 + (tid >> 5);
    int lane = tid & 31;
    if (node >= n) return;
    float a0 = 0.f, a1 = 0.f, a2 = 0.f, a3 = 0.f;
    const float* xr = g_x1 + (size_t)node * 256;
    for (int k = lane; k < 256; k += 32) {
        float x = xr[k];
        float4 w = sW[k];
        a0 = fmaf(x, w.x, a0); a1 = fmaf(x, w.y, a1);
        a2 = fmaf(x, w.z, a2); a3 = fmaf(x, w.w, a3);
    }
#pragma unroll
    for (int o = 16; o; o >>= 1) {
        a0 += __shfl_xor_sync(0xffffffffu, a0, o);
        a1 += __shfl_xor_sync(0xffffffffu, a1, o);
        a2 += __shfl_xor_sync(0xffffffffu, a2, o);
        a3 += __shfl_xor_sync(0xffffffffu, a3, o);
    }
    if (lane == 0) {
        *(float4*)(g_h2 + (size_t)node * 4) = make_float4(a0, a1, a2, a3);
        g_as2[node] = a0 * s_as.x + a1 * s_as.y + a2 * s_as.z + a3 * s_as.w;
        g_ad2[node] = a0 * s_ad.x + a1 * s_ad.y + a2 * s_ad.z + a3 * s_ad.w;
    }
}

// ---------------- GAT2 aggregate -> final output ------------------------------
__global__ __launch_bounds__(256) void gat2_kernel(
    const float* __restrict__ g2_b, float* __restrict__ out, int n)
{
    int node = blockIdx.x * 8 + (threadIdx.x >> 5);
    int lane = threadIdx.x & 31;
    if (node >= n) return;
    int beg = g_rowptr[node], end = g_rowptr[node + 1];
    float adv = g_ad2[node];

    float m = -1e30f;
    for (int i = beg + lane; i < end; i += 32) {
        int s = g_csr[i];
        m = fmaxf(m, lrelu(g_as2[s] + adv));
    }
#pragma unroll
    for (int o = 16; o; o >>= 1) m = fmaxf(m, __shfl_xor_sync(0xffffffffu, m, o));

    float ssum = 0.f, a0 = 0.f, a1 = 0.f, a2 = 0.f, a3 = 0.f;
    for (int i = beg + lane; i < end; i += 32) {
        int s = g_csr[i];
        float w = expf(lrelu(g_as2[s] + adv) - m);
        ssum += w;
        float4 hv = *(const float4*)(g_h2 + (size_t)s * 4);
        a0 = fmaf(w, hv.x, a0); a1 = fmaf(w, hv.y, a1);
        a2 = fmaf(w, hv.z, a2); a3 = fmaf(w, hv.w, a3);
    }
#pragma unroll
    for (int o = 16; o; o >>= 1) {
        ssum += __shfl_xor_sync(0xffffffffu, ssum, o);
        a0 += __shfl_xor_sync(0xffffffffu, a0, o);
        a1 += __shfl_xor_sync(0xffffffffu, a1, o);
        a2 += __shfl_xor_sync(0xffffffffu, a2, o);
        a3 += __shfl_xor_sync(0xffffffffu, a3, o);
    }
    if (lane == 0) {
        float inv = 1.f / (ssum + 1e-16f);
        float4 o4 = make_float4(a0 * inv + g2_b[0], a1 * inv + g2_b[1],
                                a2 * inv + g2_b[2], a3 * inv + g2_b[3]);
        *(float4*)(out + (size_t)node * 4) = o4;
    }
}

// ---------------- launch -------------------------------------------------------
extern "C" void kernel_launch(void* const* d_in, const int* in_sizes, int n_in,
                              void* d_out, int out_size)
{
    (void)n_in; (void)out_size;
    const float* text     = (const float*)d_in[0];
    const float* mel      = (const float*)d_in[1];
    const int*   ei       = (const int*)  d_in[2];
    const float* mel_W    = (const float*)d_in[3];
    const float* mel_b    = (const float*)d_in[4];
    const float* concat_W = (const float*)d_in[5];
    const float* concat_b = (const float*)d_in[6];
    const float* g1_W     = (const float*)d_in[7];
    const float* g1_as    = (const float*)d_in[8];
    const float* g1_ad    = (const float*)d_in[9];
    const float* g1_b     = (const float*)d_in[10];
    const float* g2_W     = (const float*)d_in[11];
    const float* g2_as    = (const float*)d_in[12];
    const float* g2_ad    = (const float*)d_in[13];
    const float* g2_b     = (const float*)d_in[14];
    float* out = (float*)d_out;

    const int n    = in_sizes[0] / TXT;       // 20000
    const int E    = in_sizes[2] / 2;         // 640000
    const int Etot = E + n;                   // 660000

    float *p_melf, *p_x0, *p_part;
    __half* p_h1h;
    uint32_t *p_Wh, *p_Whc;
    cudaGetSymbolAddress((void**)&p_melf, g_melf);
    cudaGetSymbolAddress((void**)&p_x0,   g_x0);
    cudaGetSymbolAddress((void**)&p_part, g_part);
    cudaGetSymbolAddress((void**)&p_h1h,  g_h1h);
    cudaGetSymbolAddress((void**)&p_Wh,   g_Wh);
    cudaGetSymbolAddress((void**)&p_Whc,  g_Whc);

    cudaFuncSetAttribute(mmagemm_h,
                         cudaFuncAttributeMaxDynamicSharedMemorySize, HSMEM);

    // side stream + events for CSR overlap (created once; reused in capture)
    static cudaStream_t s_side = nullptr;
    static cudaEvent_t  ev_fork = nullptr, ev_join = nullptr;
    if (!s_side) {
        cudaStreamCreateWithFlags(&s_side, cudaStreamNonBlocking);
        cudaEventCreateWithFlags(&ev_fork, cudaEventDisableTiming);
        cudaEventCreateWithFlags(&ev_join, cudaEventDisableTiming);
    }

    const int tiles128 = (n + 127) / 128;     // 157
    const int mblocks  = (n + BM - 1) / BM;   // 313
    const int total4   = n * HID / 4;
    const int stride4  = n * HID / 4;

    // main #1: W prep for mel
    wprep_h<<<(HID * MELK / 2 + 255) / 256, 256>>>(mel_W, p_Wh, MELK);

    // fork side stream: CSR build runs concurrently with the GEMM pipeline
    cudaEventRecord(ev_fork, 0);
    cudaStreamWaitEvent(s_side, ev_fork, 0);
    init_deg_kernel<<<(n + 255) / 256, 256, 0, s_side>>>(n);
    hist_kernel<<<(Etot + 255) / 256, 256, 0, s_side>>>(ei, E, Etot);

    // mel_feat = relu(mel @ mel_W + mel_b): fp16 mma.sync 128-tile, 4-way K-split
    mmagemm_h<<<dim3(tiles128, 1, 4), 256, HSMEM>>>(
        mel, MELK, MELK, mel, MELK, p_Wh, nullptr,
        nullptr, HID, p_part, n, MELK, MELK / 4, 0);
    combine_kernel<<<(total4 + 255) / 256, 256>>>(4, total4, mel_b, p_melf, 1, stride4);

    scan_kernel<<<1, 1024, 0, s_side>>>(n);
    scatter_kernel<<<(Etot + 255) / 256, 256, 0, s_side>>>(ei, E, Etot);
    cudaEventRecord(ev_join, s_side);

    // x0 = elu([text | mel_feat] @ concat_W + concat_b): 128-tile, 2-way K-split
    wprep_h<<<(HID * (TXT + HID) / 2 + 255) / 256, 256>>>(concat_W, p_Whc, TXT + HID);
    mmagemm_h<<<dim3(tiles128, 1, 2), 256, HSMEM>>>(
        text, TXT, TXT, p_melf, HID, p_Whc, nullptr,
        nullptr, HID, p_part, n, TXT + HID, (TXT + HID) / 2, 0);
    combine_kernel<<<(total4 + 255) / 256, 256>>>(2, total4, concat_b, p_x0, 2, stride4);

    // h1 = x0 @ g1_W (fp32 accum, fp16 storage)
    gemm2_kernel<<<dim3(mblocks, 2), 128>>>(p_x0, HID, HID, p_x0, HID,
                                            g1_W, 256, nullptr,
                                            (float*)p_h1h, 256, n, HID, 0, 1);

    att1_kernel<<<(2 * n + 7) / 8, 256>>>(g1_as, g1_ad, n);

    // join: gat1 needs the CSR
    cudaStreamWaitEvent(0, ev_join, 0);
    gat1_kernel<<<(2 * n + 7) / 8, 256>>>(g1_b, n);
    h2_kernel<<<(n + 7) / 8, 256>>>(g2_W, g2_as, g2_ad, n);
    gat2_kernel<<<(n + 7) / 8, 256>>>(g2_b, out, n);
}

// round 16
// speedup vs baseline: 1.3311x; 1.0138x over previous
#include <cuda_runtime.h>
#include <cuda_fp16.h>
#include <math.h>
#include <stdint.h>

// Problem constants (fixed shapes for this problem)
#define NN    20000
#define EE    640000
#define ETOT0 (EE + NN)
#define TXT   768
#define MELK  6400
#define HID   128

typedef unsigned long long ull;

// ---------------- scratch (static device globals; no allocation) -------------
__device__ float    g_melf[NN * HID];     // relu(mel @ mel_W + b)
__device__ float    g_x0  [NN * HID];     // elu(concat @ concat_W + b)
__device__ float    g_part[4 * NN * HID]; // K-split GEMM partials (40MB)
__device__ __half   g_h1h [NN * 256];     // x0 @ g1_W  (fp16 storage)
__device__ float    g_x1  [NN * 256];     // GAT1 output (after elu)
__device__ uint32_t g_Wh  [HID * MELK / 2];        // mel_W^T f16x2, k-permuted
__device__ uint32_t g_Whc [HID * (TXT + HID) / 2]; // concat_W^T f16x2, k-permuted
__device__ float    g_as1 [NN * 2];
__device__ float    g_ad1 [NN * 2];
__device__ float    g_h2  [NN * 4];
__device__ float    g_as2 [NN];
__device__ float    g_ad2 [NN];
__device__ int      g_deg [NN];
__device__ int      g_rowptr[NN + 1];
__device__ int      g_cursor[NN];
__device__ int      g_csr[ETOT0];

__device__ __forceinline__ float eluf(float x) { return x > 0.f ? x : expm1f(x); }
__device__ __forceinline__ float lrelu(float x) { return x > 0.f ? x : 0.2f * x; }

// ---- packed f32x2 helpers ------------------------------------------------------
__device__ __forceinline__ ull bcast2(float x) {
    ull r; unsigned u = __float_as_uint(x);
    asm("mov.b64 %0, {%1, %1};" : "=l"(r) : "r"(u));
    return r;
}
__device__ __forceinline__ void fma2(ull& d, ull a, ull b) {
    asm("fma.rn.f32x2 %0, %1, %2, %0;" : "+l"(d) : "l"(a), "l"(b));
}
__device__ __forceinline__ float2 unpack2(ull v) {
    unsigned lo, hi;
    asm("mov.b64 {%0, %1}, %2;" : "=r"(lo), "=r"(hi) : "l"(v));
    float2 f; f.x = __uint_as_float(lo); f.y = __uint_as_float(hi);
    return f;
}

// ---- mma.sync / cp.async helpers ------------------------------------------------
__device__ __forceinline__ uint32_t smem_u32(const void* p) {
    uint32_t a;
    asm("{ .reg .u64 t; cvta.to.shared.u64 t, %1; cvt.u32.u64 %0, t; }"
        : "=r"(a) : "l"(p));
    return a;
}
__device__ __forceinline__ void cp16(uint32_t dst, const void* src) {
    asm volatile("cp.async.cg.shared.global [%0], [%1], 16;"
                 :: "r"(dst), "l"(src) : "memory");
}
__device__ __forceinline__ void mma16(float* c, const uint32_t* a, const uint32_t* b) {
    asm volatile(
        "mma.sync.aligned.m16n8k16.row.col.f32.f16.f16.f32 "
        "{%0,%1,%2,%3}, {%4,%5,%6,%7}, {%8,%9}, {%0,%1,%2,%3};"
        : "+f"(c[0]), "+f"(c[1]), "+f"(c[2]), "+f"(c[3])
        : "r"(a[0]), "r"(a[1]), "r"(a[2]), "r"(a[3]), "r"(b[0]), "r"(b[1]));
}
// pack (lo, hi) floats -> f16x2 word (lo in low half)
__device__ __forceinline__ uint32_t f16x2(float lo, float hi) {
    uint32_t r;
    asm("cvt.rn.f16x2.f32 %0, %1, %2;" : "=r"(r) : "f"(hi), "f"(lo));
    return r;
}

// ---------------- W prep: transpose + fp16 pack, k-word permuted -------------------
// Layout: Wh[n][c][p], p = 0..15 words per 32-k chunk. Word position p holds
// original k-pair word w = 8*(p>>3) + ((p&7)>>1) + 4*(p&1), so that an LDS.64 at
// p = 8s+2t yields the (b0, b1) fragment pair (orig words kc, kc+4) in one load.
__global__ void wprep_h(const float* __restrict__ W, uint32_t* __restrict__ Wh, int K)
{
    int i = blockIdx.x * 256 + threadIdx.x;
    const int kw = K / 2;
    if (i >= HID * kw) return;
    int n = i / kw, rem = i - n * kw;
    int c = rem >> 4, p = rem & 15;
    int s = p >> 3, q = p & 7;
    int w = 8 * s + (q >> 1) + 4 * (q & 1);
    int k0 = c * 32 + 2 * w;
    float w0 = W[(size_t)k0 * HID + n];
    float w1 = W[(size_t)(k0 + 1) * HID + n];
    Wh[i] = f16x2(w0, w1);
}

// ---------------- fp16 mma GEMM v4: register convert, one barrier/chunk ------------
// Per split: partial[M,128] = A[M, koff:koff+klen] @ W-chunk (raw fp32 partials).
// If Part==null: writes act(acc + bias) directly to C.
// CTA: 128x128 tile, 256 thr (8 warps, 4m x 2n of 32x64 warp tiles), K chunks of 32.
// A: cp.async f32 (3 stages) -> per-thread LDS.64 + cvt into fragment registers.
// W: cp.async fp16 (3 stages, k-permuted) -> LDS.64 fragment pairs.
#define HSTG_A32  (128 * 36)                       // floats per f32 A stage (18432B)
#define OFF_BUFW  (3 * HSTG_A32 * 4)               // 55296
#define HSMEM     (OFF_BUFW + 3 * 10240)           // 86016 bytes -> 2 CTAs/SM

__global__ __launch_bounds__(256, 2) void mmagemm_h(
    const float* __restrict__ A1, int lda1, int ksplit,
    const float* __restrict__ A2, int lda2,
    const uint32_t* __restrict__ Wh,
    const float* __restrict__ bias,
    float* __restrict__ C, int ldc,
    float* __restrict__ Part,
    int M, int Ktot, int klen, int act)
{
    extern __shared__ char smem[];
    const uint32_t sb = smem_u32(smem);
    const int tid  = threadIdx.x;
    const int lane = tid & 31, wid = tid >> 5;
    const int g    = lane >> 2, t = lane & 3;
    const int wm   = wid & 3, wn = wid >> 2;       // 4m x 2n warp grid
    const int mbase = blockIdx.x * 128;
    const int split = blockIdx.z;
    const int koff  = split * klen;
    const int nch   = klen >> 5;

    // cp.async A mapping: 4 rows (crow+32j), 16B at ccol
    const int crow = tid >> 3;
    const int ccol = (tid & 7) * 4;
    // cp.async W mapping: row = tid>>1, seg = tid&1 (2x16B each)
    const int wrow = tid >> 1;
    const int wseg = tid & 1;

    float acc[2][8][4];
#pragma unroll
    for (int i = 0; i < 2; i++)
#pragma unroll
        for (int j = 0; j < 8; j++)
#pragma unroll
            for (int q = 0; q < 4; q++) acc[i][j][q] = 0.f;

    auto issue = [&](int c) {
        // A f32 -> stage c%3
        const uint32_t ba = sb + (uint32_t)(c % 3) * (HSTG_A32 * 4);
        const int k0 = koff + c * 32;
#pragma unroll
        for (int j = 0; j < 4; j++) {
            const int row = crow + j * 32;
            int gr = mbase + row; if (gr > M - 1) gr = M - 1;
            const int gk = k0 + ccol;
            const float* src = (gk < ksplit)
                ? (A1 + (size_t)gr * lda1 + gk)
                : (A2 + (size_t)gr * lda2 + (gk - ksplit));
            cp16(ba + (uint32_t)(row * 36 + ccol) * 4, src);
        }
        // W f16 -> bufW c%3 (64B data per row, 80B row stride)
        const uint32_t bw = sb + OFF_BUFW + (uint32_t)(c % 3) * 10240;
        const uint32_t* srcW = Wh + (size_t)wrow * (Ktot >> 1) + c * 16 + (k0 - koff - c * 32) + wseg * 8
                               + (size_t)(koff >> 1);   // = wrow*(Ktot/2) + (koff + c*32)/2 + wseg*8
        cp16(bw + wrow * 80 + wseg * 32, srcW);
        cp16(bw + wrow * 80 + wseg * 32 + 16, srcW + 4);
        asm volatile("cp.async.commit_group;" ::: "memory");
    };

    issue(0);
    if (nch > 1) issue(1);

    const int r0    = wm * 32 + g;
    const int bbase0 = (wn * 64 + g) * 20;

    for (int c = 0; c < nch; c++) {
        if (c + 1 < nch) asm volatile("cp.async.wait_group 1;" ::: "memory");
        else             asm volatile("cp.async.wait_group 0;" ::: "memory");
        __syncthreads();
        if (c + 2 < nch) issue(c + 2);

        const float*    As32 = (const float*)(smem) + (c % 3) * HSTG_A32;
        const uint32_t* Bh   = (const uint32_t*)(smem + OFF_BUFW + (c % 3) * 10240);

#pragma unroll
        for (int s = 0; s < 2; s++) {
            // ---- A fragments: LDS.64 f32 pairs -> cvt in registers ----
            uint32_t a[2][4];
#pragma unroll
            for (int mt = 0; mt < 2; mt++) {
                const float* base = As32 + (r0 + mt * 16) * 36 + 2 * t + 16 * s;
                float2 v00 = *(const float2*)(base);            // row r,   k=16s+2t
                float2 v10 = *(const float2*)(base + 8 * 36);   // row r+8, k=16s+2t
                float2 v01 = *(const float2*)(base + 8);        // row r,   k=16s+2t+8
                float2 v11 = *(const float2*)(base + 8 * 36 + 8);
                a[mt][0] = f16x2(v00.x, v00.y);
                a[mt][1] = f16x2(v10.x, v10.y);
                a[mt][2] = f16x2(v01.x, v01.y);
                a[mt][3] = f16x2(v11.x, v11.y);
            }
            // ---- B fragments: one LDS.64 per nt (k-permuted layout) ----
            uint2 bw[8];
            const int bofs = bbase0 + 8 * s + 2 * t;
#pragma unroll
            for (int nt = 0; nt < 8; nt++)
                bw[nt] = *(const uint2*)(Bh + bofs + nt * 160);  // +8 rows * 20 words
#pragma unroll
            for (int mt = 0; mt < 2; mt++)
#pragma unroll
                for (int nt = 0; nt < 8; nt++) {
                    uint32_t bb[2] = {bw[nt].x, bw[nt].y};
                    mma16(acc[mt][nt], a[mt], bb);
                }
        }
    }

    // ---- epilogue ----
#pragma unroll
    for (int mt = 0; mt < 2; mt++) {
        const int row = mbase + wm * 32 + mt * 16 + g;
#pragma unroll
        for (int nt = 0; nt < 8; nt++) {
            const int col = wn * 64 + nt * 8 + 2 * t;
            if (Part) {
                float* dst = Part + ((size_t)split * M + row) * 128 + col;
                if (row < M)     *(float2*)(dst)           = make_float2(acc[mt][nt][0], acc[mt][nt][1]);
                if (row + 8 < M) *(float2*)(dst + 8 * 128) = make_float2(acc[mt][nt][2], acc[mt][nt][3]);
            } else {
                float b0 = bias[col], b1 = bias[col + 1];
                float v0 = acc[mt][nt][0] + b0, v1 = acc[mt][nt][1] + b1;
                float v2 = acc[mt][nt][2] + b0, v3 = acc[mt][nt][3] + b1;
                if (act == 1) {
                    v0 = fmaxf(v0, 0.f); v1 = fmaxf(v1, 0.f);
                    v2 = fmaxf(v2, 0.f); v3 = fmaxf(v3, 0.f);
                } else {
                    v0 = eluf(v0); v1 = eluf(v1); v2 = eluf(v2); v3 = eluf(v3);
                }
                if (row < M)     *(float2*)(C + (size_t)row * ldc + col)       = make_float2(v0, v1);
                if (row + 8 < M) *(float2*)(C + (size_t)(row + 8) * ldc + col) = make_float2(v2, v3);
            }
        }
    }
}

// ---------------- combine K-split partials: dst = act(sum + bias) -------------
__global__ void combine_kernel(int nsplit, int total4, const float* __restrict__ bias,
                               float* __restrict__ dst, int act, int stride4)
{
    int i = blockIdx.x * blockDim.x + threadIdx.x;
    if (i >= total4) return;
    const float4* p = (const float4*)g_part;
    float4 v = p[i];
    for (int s = 1; s < nsplit; s++) {
        float4 w = p[i + s * stride4];
        v.x += w.x; v.y += w.y; v.z += w.z; v.w += w.w;
    }
    const int col = (i * 4) & 127;   // ldc = 128
    v.x += bias[col]; v.y += bias[col + 1]; v.z += bias[col + 2]; v.w += bias[col + 3];
    if (act == 1) {
        v.x = fmaxf(v.x, 0.f); v.y = fmaxf(v.y, 0.f); v.z = fmaxf(v.z, 0.f); v.w = fmaxf(v.w, 0.f);
    } else {
        v.x = eluf(v.x); v.y = eluf(v.y); v.z = eluf(v.z); v.w = eluf(v.w);
    }
    ((float4*)dst)[i] = v;
}

// ---------------- GEMM v2 (exact fp32 accum, f32x2) — used for g1 --------------
#define BM 64
#define BN 128
#define BK 16
#define ASTRIDE 68

__global__ __launch_bounds__(128, 3) void gemm2_kernel(
    const float* __restrict__ A1, int lda1, int ksplit,
    const float* __restrict__ A2, int lda2,
    const float* __restrict__ W, int ldw,
    const float* __restrict__ bias,
    float* __restrict__ C, int ldc,
    int M, int klen, int act, int out_half)
{
    __shared__ float As[BK][ASTRIDE];
    __shared__ float Bs[BK][BN];
    const int tid    = threadIdx.x;
    const int brow   = blockIdx.x * BM;
    const int colOff = blockIdx.y * BN;

    const int tr = tid >> 4;
    const int tc = tid & 15;

    ull acc[8][4];
#pragma unroll
    for (int i = 0; i < 8; i++)
#pragma unroll
        for (int j = 0; j < 4; j++) acc[i][j] = 0ULL;

    const int ar0 = tid >> 2;
    const int ac4 = (tid & 3) * 4;
    const int bq  = (tid & 31) * 4;
    const int br0 = tid >> 5;

    for (int k0 = 0; k0 < klen; k0 += BK) {
#pragma unroll
        for (int h = 0; h < 2; h++) {
            const int row = ar0 + h * 32;
            const int gr  = brow + row;
            const int gk  = k0 + ac4;
            float4 v = make_float4(0.f, 0.f, 0.f, 0.f);
            if (gr < M) {
                const float* p = (gk < ksplit)
                    ? (A1 + (size_t)gr * lda1 + gk)
                    : (A2 + (size_t)gr * lda2 + (gk - ksplit));
                v = *(const float4*)p;
            }
            As[ac4 + 0][row] = v.x;
            As[ac4 + 1][row] = v.y;
            As[ac4 + 2][row] = v.z;
            As[ac4 + 3][row] = v.w;
        }
#pragma unroll
        for (int j = 0; j < 4; j++) {
            const int row = br0 + j * 4;
            const float4 v = *(const float4*)(W + (size_t)(k0 + row) * ldw
                                              + colOff + bq);
            *(float4*)&Bs[row][bq] = v;
        }
        __syncthreads();

#pragma unroll
        for (int kk = 0; kk < BK; kk++) {
            float a[8];
            *(float4*)(a)     = *(const float4*)&As[kk][tr * 8];
            *(float4*)(a + 4) = *(const float4*)&As[kk][tr * 8 + 4];
            ulonglong2 bA = *(const ulonglong2*)&Bs[kk][tc * 4];
            ulonglong2 bB = *(const ulonglong2*)&Bs[kk][64 + tc * 4];
#pragma unroll
            for (int i = 0; i < 8; i++) {
                ull av = bcast2(a[i]);
                fma2(acc[i][0], av, bA.x);
                fma2(acc[i][1], av, bA.y);
                fma2(acc[i][2], av, bB.x);
                fma2(acc[i][3], av, bB.y);
            }
        }
        __syncthreads();
    }

#pragma unroll
    for (int i = 0; i < 8; i++) {
        const int gr = brow + tr * 8 + i;
        if (gr >= M) continue;
        float2 p0 = unpack2(acc[i][0]), p1 = unpack2(acc[i][1]);
        float2 p2 = unpack2(acc[i][2]), p3 = unpack2(acc[i][3]);
        float4 v0 = make_float4(p0.x, p0.y, p1.x, p1.y);
        float4 v1 = make_float4(p2.x, p2.y, p3.x, p3.y);
        const int c0 = colOff + tc * 4;
        const int c1 = colOff + 64 + tc * 4;
        if (bias) {
            v0.x += bias[c0]; v0.y += bias[c0 + 1]; v0.z += bias[c0 + 2]; v0.w += bias[c0 + 3];
            v1.x += bias[c1]; v1.y += bias[c1 + 1]; v1.z += bias[c1 + 2]; v1.w += bias[c1 + 3];
        }
        if (act == 1) {
            v0.x = fmaxf(v0.x, 0.f); v0.y = fmaxf(v0.y, 0.f); v0.z = fmaxf(v0.z, 0.f); v0.w = fmaxf(v0.w, 0.f);
            v1.x = fmaxf(v1.x, 0.f); v1.y = fmaxf(v1.y, 0.f); v1.z = fmaxf(v1.z, 0.f); v1.w = fmaxf(v1.w, 0.f);
        } else if (act == 2) {
            v0.x = eluf(v0.x); v0.y = eluf(v0.y); v0.z = eluf(v0.z); v0.w = eluf(v0.w);
            v1.x = eluf(v1.x); v1.y = eluf(v1.y); v1.z = eluf(v1.z); v1.w = eluf(v1.w);
        }
        if (out_half) {
            __half* dst = (__half*)C + (size_t)gr * ldc;
            uint2 h0, h1;
            h0.x = f16x2(v0.x, v0.y); h0.y = f16x2(v0.z, v0.w);
            h1.x = f16x2(v1.x, v1.y); h1.y = f16x2(v1.z, v1.w);
            *(uint2*)(dst + c0) = h0;
            *(uint2*)(dst + c1) = h1;
        } else {
            float* dst = C + (size_t)gr * ldc;
            *(float4*)(dst + c0) = v0;
            *(float4*)(dst + c1) = v1;
        }
    }
}

// ---------------- CSR build ---------------------------------------------------
__global__ void init_deg_kernel(int n)
{
    int i = blockIdx.x * blockDim.x + threadIdx.x;
    if (i < n) g_deg[i] = 0;
}

__global__ void hist_kernel(const int* __restrict__ ei, int E, int Etot)
{
    int e = blockIdx.x * blockDim.x + threadIdx.x;
    if (e >= Etot) return;
    int dst = (e < E) ? ei[E + e] : (e - E);
    atomicAdd(&g_deg[dst], 1);
}

__global__ __launch_bounds__(1024) void scan_kernel(int n)
{
    __shared__ int sb[1024];
    const int tid = threadIdx.x;
    const int CH  = (NN + 1023) / 1024;   // 20
    int local[CH];
    int base = tid * CH;
    int sum = 0;
#pragma unroll
    for (int j = 0; j < CH; j++) {
        int idx = base + j;
        int v = (idx < n) ? g_deg[idx] : 0;
        local[j] = v;
        sum += v;
    }
    sb[tid] = sum;
    __syncthreads();
    for (int off = 1; off < 1024; off <<= 1) {
        int v = (tid >= off) ? sb[tid - off] : 0;
        __syncthreads();
        sb[tid] += v;
        __syncthreads();
    }
    int run = sb[tid] - sum;
#pragma unroll
    for (int j = 0; j < CH; j++) {
        int idx = base + j;
        if (idx < n) {
            g_rowptr[idx] = run;
            g_cursor[idx] = run;
            run += local[j];
        }
    }
    if (tid == 1023) g_rowptr[n] = sb[1023];
}

__global__ void scatter_kernel(const int* __restrict__ ei, int E, int Etot)
{
    int e = blockIdx.x * blockDim.x + threadIdx.x;
    if (e >= Etot) return;
    int src, dst;
    if (e < E) { src = ei[e]; dst = ei[E + e]; }
    else       { src = e - E; dst = e - E; }
    int pos = atomicAdd(&g_cursor[dst], 1);
    g_csr[pos] = src;
}

// ---------------- GAT1 attention coefficients (h1 in fp16) --------------------
__global__ __launch_bounds__(256) void att1_kernel(
    const float* __restrict__ g1_as, const float* __restrict__ g1_ad, int n)
{
    int p = blockIdx.x * 8 + (threadIdx.x >> 5);
    int lane = threadIdx.x & 31;
    if (p >= n * 2) return;
    int node = p >> 1, h = p & 1;
    uint2 r = *(const uint2*)(g_h1h + (size_t)node * 256 + h * 128 + lane * 4);
    float2 f0 = __half22float2(*(__half2*)&r.x);
    float2 f1 = __half22float2(*(__half2*)&r.y);
    float4 as = *(const float4*)(g1_as + h * 128 + lane * 4);
    float4 ad = *(const float4*)(g1_ad + h * 128 + lane * 4);
    float vs = f0.x * as.x + f0.y * as.y + f1.x * as.z + f1.y * as.w;
    float vd = f0.x * ad.x + f0.y * ad.y + f1.x * ad.z + f1.y * ad.w;
#pragma unroll
    for (int o = 16; o; o >>= 1) {
        vs += __shfl_xor_sync(0xffffffffu, vs, o);
        vd += __shfl_xor_sync(0xffffffffu, vd, o);
    }
    if (lane == 0) { g_as1[p] = vs; g_ad1[p] = vd; }
}

// ---------------- GAT1 aggregate (atomic-free via CSR, fp16 values) ------------
__global__ __launch_bounds__(256) void gat1_kernel(const float* __restrict__ g1_b, int n)
{
    int p = blockIdx.x * 8 + (threadIdx.x >> 5);
    int lane = threadIdx.x & 31;
    if (p >= n * 2) return;
    int node = p >> 1, h = p & 1;
    int beg = g_rowptr[node], end = g_rowptr[node + 1];
    float adv = g_ad1[node * 2 + h];

    float m = -1e30f;
    for (int i = beg + lane; i < end; i += 32) {
        int s = g_csr[i];
        m = fmaxf(m, lrelu(g_as1[s * 2 + h] + adv));
    }
#pragma unroll
    for (int o = 16; o; o >>= 1) m = fmaxf(m, __shfl_xor_sync(0xffffffffu, m, o));

    float ssum = 0.f, ax = 0.f, ay = 0.f, az = 0.f, aw = 0.f;
    const __half* hb = g_h1h + h * 128 + lane * 4;
    for (int i = beg; i < end; ++i) {
        int s = g_csr[i];                                // broadcast load
        float w = expf(lrelu(g_as1[s * 2 + h] + adv) - m);
        ssum += w;
        uint2 r = *(const uint2*)(hb + (size_t)s * 256);
        float2 f0 = __half22float2(*(__half2*)&r.x);
        float2 f1 = __half22float2(*(__half2*)&r.y);
        ax = fmaf(w, f0.x, ax); ay = fmaf(w, f0.y, ay);
        az = fmaf(w, f1.x, az); aw = fmaf(w, f1.y, aw);
    }
    float inv = 1.f / (ssum + 1e-16f);
    int col = h * 128 + lane * 4;
    float4 o;
    o.x = eluf(ax * inv + g1_b[col + 0]);
    o.y = eluf(ay * inv + g1_b[col + 1]);
    o.z = eluf(az * inv + g1_b[col + 2]);
    o.w = eluf(aw * inv + g1_b[col + 3]);
    *(float4*)(g_x1 + (size_t)node * 256 + col) = o;
}

// ---------------- GAT2 projection + attention coefficients --------------------
__global__ __launch_bounds__(256) void h2_kernel(
    const float* __restrict__ g2_W, const float* __restrict__ g2_as,
    const float* __restrict__ g2_ad, int n)
{
    __shared__ float4 sW[256];
    __shared__ float4 s_as, s_ad;
    const int tid = threadIdx.x;
    sW[tid] = *(const float4*)(g2_W + tid * 4);
    if (tid == 0) { s_as = *(const float4*)g2_as; s_ad = *(const float4*)g2_ad; }
    __syncthreads();
    int node = blockIdx.x * 8 + (tid >> 5);
    int lane = tid & 31;
    if (node >= n) return;
    float a0 = 0.f, a1 = 0.f, a2 = 0.f, a3 = 0.f;
    const float* xr = g_x1 + (size_t)node * 256;
    for (int k = lane; k < 256; k += 32) {
        float x = xr[k];
        float4 w = sW[k];
        a0 = fmaf(x, w.x, a0); a1 = fmaf(x, w.y, a1);
        a2 = fmaf(x, w.z, a2); a3 = fmaf(x, w.w, a3);
    }
#pragma unroll
    for (int o = 16; o; o >>= 1) {
        a0 += __shfl_xor_sync(0xffffffffu, a0, o);
        a1 += __shfl_xor_sync(0xffffffffu, a1, o);
        a2 += __shfl_xor_sync(0xffffffffu, a2, o);
        a3 += __shfl_xor_sync(0xffffffffu, a3, o);
    }
    if (lane == 0) {
        *(float4*)(g_h2 + (size_t)node * 4) = make_float4(a0, a1, a2, a3);
        g_as2[node] = a0 * s_as.x + a1 * s_as.y + a2 * s_as.z + a3 * s_as.w;
        g_ad2[node] = a0 * s_ad.x + a1 * s_ad.y + a2 * s_ad.z + a3 * s_ad.w;
    }
}

// ---------------- GAT2 aggregate -> final output ------------------------------
__global__ __launch_bounds__(256) void gat2_kernel(
    const float* __restrict__ g2_b, float* __restrict__ out, int n)
{
    int node = blockIdx.x * 8 + (threadIdx.x >> 5);
    int lane = threadIdx.x & 31;
    if (node >= n) return;
    int beg = g_rowptr[node], end = g_rowptr[node + 1];
    float adv = g_ad2[node];

    float m = -1e30f;
    for (int i = beg + lane; i < end; i += 32) {
        int s = g_csr[i];
        m = fmaxf(m, lrelu(g_as2[s] + adv));
    }
#pragma unroll
    for (int o = 16; o; o >>= 1) m = fmaxf(m, __shfl_xor_sync(0xffffffffu, m, o));

    float ssum = 0.f, a0 = 0.f, a1 = 0.f, a2 = 0.f, a3 = 0.f;
    for (int i = beg + lane; i < end; i += 32) {
        int s = g_csr[i];
        float w = expf(lrelu(g_as2[s] + adv) - m);
        ssum += w;
        float4 hv = *(const float4*)(g_h2 + (size_t)s * 4);
        a0 = fmaf(w, hv.x, a0); a1 = fmaf(w, hv.y, a1);
        a2 = fmaf(w, hv.z, a2); a3 = fmaf(w, hv.w, a3);
    }
#pragma unroll
    for (int o = 16; o; o >>= 1) {
        ssum += __shfl_xor_sync(0xffffffffu, ssum, o);
        a0 += __shfl_xor_sync(0xffffffffu, a0, o);
        a1 += __shfl_xor_sync(0xffffffffu, a1, o);
        a2 += __shfl_xor_sync(0xffffffffu, a2, o);
        a3 += __shfl_xor_sync(0xffffffffu, a3, o);
    }
    if (lane == 0) {
        float inv = 1.f / (ssum + 1e-16f);
        float4 o4 = make_float4(a0 * inv + g2_b[0], a1 * inv + g2_b[1],
                                a2 * inv + g2_b[2], a3 * inv + g2_b[3]);
        *(float4*)(out + (size_t)node * 4) = o4;
    }
}

// ---------------- launch -------------------------------------------------------
extern "C" void kernel_launch(void* const* d_in, const int* in_sizes, int n_in,
                              void* d_out, int out_size)
{
    (void)n_in; (void)out_size;
    const float* text     = (const float*)d_in[0];
    const float* mel      = (const float*)d_in[1];
    const int*   ei       = (const int*)  d_in[2];
    const float* mel_W    = (const float*)d_in[3];
    const float* mel_b    = (const float*)d_in[4];
    const float* concat_W = (const float*)d_in[5];
    const float* concat_b = (const float*)d_in[6];
    const float* g1_W     = (const float*)d_in[7];
    const float* g1_as    = (const float*)d_in[8];
    const float* g1_ad    = (const float*)d_in[9];
    const float* g1_b     = (const float*)d_in[10];
    const float* g2_W     = (const float*)d_in[11];
    const float* g2_as    = (const float*)d_in[12];
    const float* g2_ad    = (const float*)d_in[13];
    const float* g2_b     = (const float*)d_in[14];
    float* out = (float*)d_out;

    const int n    = in_sizes[0] / TXT;       // 20000
    const int E    = in_sizes[2] / 2;         // 640000
    const int Etot = E + n;                   // 660000

    float *p_melf, *p_x0, *p_part;
    __half* p_h1h;
    uint32_t *p_Wh, *p_Whc;
    cudaGetSymbolAddress((void**)&p_melf, g_melf);
    cudaGetSymbolAddress((void**)&p_x0,   g_x0);
    cudaGetSymbolAddress((void**)&p_part, g_part);
    cudaGetSymbolAddress((void**)&p_h1h,  g_h1h);
    cudaGetSymbolAddress((void**)&p_Wh,   g_Wh);
    cudaGetSymbolAddress((void**)&p_Whc,  g_Whc);

    cudaFuncSetAttribute(mmagemm_h,
                         cudaFuncAttributeMaxDynamicSharedMemorySize, HSMEM);

    // side stream + events for CSR overlap (created once; reused in capture)
    static cudaStream_t s_side = nullptr;
    static cudaEvent_t  ev_fork = nullptr, ev_join = nullptr;
    if (!s_side) {
        cudaStreamCreateWithFlags(&s_side, cudaStreamNonBlocking);
        cudaEventCreateWithFlags(&ev_fork, cudaEventDisableTiming);
        cudaEventCreateWithFlags(&ev_join, cudaEventDisableTiming);
    }

    const int tiles128 = (n + 127) / 128;     // 157
    const int mblocks  = (n + BM - 1) / BM;   // 313
    const int total4   = n * HID / 4;
    const int stride4  = n * HID / 4;

    // main #1: W prep for mel
    wprep_h<<<(HID * MELK / 2 + 255) / 256, 256>>>(mel_W, p_Wh, MELK);

    // fork side stream: CSR build runs concurrently with the GEMM pipeline
    cudaEventRecord(ev_fork, 0);
    cudaStreamWaitEvent(s_side, ev_fork, 0);
    init_deg_kernel<<<(n + 255) / 256, 256, 0, s_side>>>(n);
    hist_kernel<<<(Etot + 255) / 256, 256, 0, s_side>>>(ei, E, Etot);

    // mel_feat = relu(mel @ mel_W + mel_b): v4, 4-way K-split
    mmagemm_h<<<dim3(tiles128, 1, 4), 256, HSMEM>>>(
        mel, MELK, MELK, mel, MELK, p_Wh, nullptr,
        nullptr, HID, p_part, n, MELK, MELK / 4, 0);
    combine_kernel<<<(total4 + 255) / 256, 256>>>(4, total4, mel_b, p_melf, 1, stride4);

    scan_kernel<<<1, 1024, 0, s_side>>>(n);
    scatter_kernel<<<(Etot + 255) / 256, 256, 0, s_side>>>(ei, E, Etot);
    cudaEventRecord(ev_join, s_side);

    // x0 = elu([text | mel_feat] @ concat_W + concat_b): v4, 2-way K-split
    wprep_h<<<(HID * (TXT + HID) / 2 + 255) / 256, 256>>>(concat_W, p_Whc, TXT + HID);
    mmagemm_h<<<dim3(tiles128, 1, 2), 256, HSMEM>>>(
        text, TXT, TXT, p_melf, HID, p_Whc, nullptr,
        nullptr, HID, p_part, n, TXT + HID, (TXT + HID) / 2, 0);
    combine_kernel<<<(total4 + 255) / 256, 256>>>(2, total4, concat_b, p_x0, 2, stride4);

    // h1 = x0 @ g1_W (fp32 accum, fp16 storage)
    gemm2_kernel<<<dim3(mblocks, 2), 128>>>(p_x0, HID, HID, p_x0, HID,
                                            g1_W, 256, nullptr,
                                            (float*)p_h1h, 256, n, HID, 0, 1);

    att1_kernel<<<(2 * n + 7) / 8, 256>>>(g1_as, g1_ad, n);

    // join: gat1 needs the CSR
    cudaStreamWaitEvent(0, ev_join, 0);
    gat1_kernel<<<(2 * n + 7) / 8, 256>>>(g1_b, n);
    h2_kernel<<<(n + 7) / 8, 256>>>(g2_W, g2_as, g2_ad, n);
    gat2_kernel<<<(n + 7) / 8, 256>>>(g2_b, out, n);
}

// round 17
// speedup vs baseline: 1.4782x; 1.1105x over previous
#include <cuda_runtime.h>
#include <cuda_fp16.h>
#include <math.h>
#include <stdint.h>

// Problem constants (fixed shapes for this problem)
#define NN    20000
#define EE    640000
#define ETOT0 (EE + NN)
#define TXT   768
#define MELK  6400
#define HID   128

typedef unsigned long long ull;

// ---------------- scratch (static device globals; no allocation) -------------
__device__ float    g_melf[NN * HID];     // relu(mel @ mel_W + b)
__device__ float    g_x0  [NN * HID];     // elu(concat @ concat_W + b)
__device__ float    g_part[4 * NN * HID]; // K-split GEMM partials (40MB)
__device__ __half   g_h1h [NN * 256];     // x0 @ g1_W  (fp16 storage)
__device__ float    g_x1  [NN * 256];     // GAT1 output (after elu)
__device__ uint32_t g_Wh  [HID * MELK / 2];        // mel_W^T f16x2 [128][K/2]
__device__ uint32_t g_Whc [HID * (TXT + HID) / 2]; // concat_W^T f16x2
__device__ float    g_as1 [NN * 2];
__device__ float    g_ad1 [NN * 2];
__device__ float    g_h2  [NN * 4];
__device__ float    g_as2 [NN];
__device__ float    g_ad2 [NN];
__device__ int      g_deg [NN];
__device__ int      g_rowptr[NN + 1];
__device__ int      g_cursor[NN];
__device__ int      g_csr[ETOT0];

__device__ __forceinline__ float eluf(float x) { return x > 0.f ? x : expm1f(x); }
__device__ __forceinline__ float lrelu(float x) { return x > 0.f ? x : 0.2f * x; }

// ---- packed f32x2 helpers ------------------------------------------------------
__device__ __forceinline__ ull bcast2(float x) {
    ull r; unsigned u = __float_as_uint(x);
    asm("mov.b64 %0, {%1, %1};" : "=l"(r) : "r"(u));
    return r;
}
__device__ __forceinline__ void fma2(ull& d, ull a, ull b) {
    asm("fma.rn.f32x2 %0, %1, %2, %0;" : "+l"(d) : "l"(a), "l"(b));
}
__device__ __forceinline__ float2 unpack2(ull v) {
    unsigned lo, hi;
    asm("mov.b64 {%0, %1}, %2;" : "=r"(lo), "=r"(hi) : "l"(v));
    float2 f; f.x = __uint_as_float(lo); f.y = __uint_as_float(hi);
    return f;
}

// ---- mma.sync / cp.async / ldmatrix helpers --------------------------------------
__device__ __forceinline__ uint32_t smem_u32(const void* p) {
    uint32_t a;
    asm("{ .reg .u64 t; cvta.to.shared.u64 t, %1; cvt.u32.u64 %0, t; }"
        : "=r"(a) : "l"(p));
    return a;
}
__device__ __forceinline__ void cp16(uint32_t dst, const void* src) {
    asm volatile("cp.async.cg.shared.global [%0], [%1], 16;"
                 :: "r"(dst), "l"(src) : "memory");
}
__device__ __forceinline__ void mma16(float* c, const uint32_t* a, const uint32_t* b) {
    asm volatile(
        "mma.sync.aligned.m16n8k16.row.col.f32.f16.f16.f32 "
        "{%0,%1,%2,%3}, {%4,%5,%6,%7}, {%8,%9}, {%0,%1,%2,%3};"
        : "+f"(c[0]), "+f"(c[1]), "+f"(c[2]), "+f"(c[3])
        : "r"(a[0]), "r"(a[1]), "r"(a[2]), "r"(a[3]), "r"(b[0]), "r"(b[1]));
}
__device__ __forceinline__ void ldm4(uint32_t* r, uint32_t addr) {
    asm volatile(
        "ldmatrix.sync.aligned.m8n8.x4.shared.b16 {%0,%1,%2,%3}, [%4];"
        : "=r"(r[0]), "=r"(r[1]), "=r"(r[2]), "=r"(r[3]) : "r"(addr));
}
// pack (lo, hi) floats -> f16x2 word (lo in low half)
__device__ __forceinline__ uint32_t f16x2(float lo, float hi) {
    uint32_t r;
    asm("cvt.rn.f16x2.f32 %0, %1, %2;" : "=r"(r) : "f"(hi), "f"(lo));
    return r;
}

// ---------------- W prep: transpose + fp16 pack (natural k order) ------------------
// W[K][128] f32 -> Wh[n][K/2] f16x2 words, k ascending per n-row.
__global__ void wprep_h(const float* __restrict__ W, uint32_t* __restrict__ Wh, int K)
{
    int i = blockIdx.x * 256 + threadIdx.x;
    const int kw = K / 2;
    if (i >= HID * kw) return;
    int n = i / kw, kp = i - n * kw;
    float w0 = W[(size_t)(2 * kp) * HID + n];
    float w1 = W[(size_t)(2 * kp + 1) * HID + n];
    Wh[i] = f16x2(w0, w1);
}

// ---------------- fp16 mma GEMM v5: ldmatrix fragments ----------------------------
// Per split: partial[M,128] = A[M, koff:koff+klen] @ W-chunk (raw fp32 partials).
// If Part==null: writes act(acc + bias) directly to C.
// CTA: 128x128 tile, 256 thr (8 warps, 4m x 2n of 32x64 warp tiles), K chunks of 32.
// A: cp.async f32 into LINEAR 128x32 stage (3x) -> packed convert -> fp16 buf (2x,
// 80B-stride rows) -> ldmatrix.x4. W: cp.async fp16 (3x, 80B rows) -> ldmatrix.x4.
#define STG32B    16384                            // f32 A stage bytes (128x32 f32)
#define OFF_BUFA  (3 * STG32B)                     // 49152
#define OFF_BUFW  (OFF_BUFA + 2 * 10240)           // 69632
#define HSMEM     (OFF_BUFW + 3 * 10240)           // 100352 bytes -> 2 CTAs/SM

__global__ __launch_bounds__(256, 2) void mmagemm_h(
    const float* __restrict__ A1, int lda1, int ksplit,
    const float* __restrict__ A2, int lda2,
    const uint32_t* __restrict__ Wh,
    const float* __restrict__ bias,
    float* __restrict__ C, int ldc,
    float* __restrict__ Part,
    int M, int Ktot, int klen, int act)
{
    extern __shared__ char smem[];
    const uint32_t sb = smem_u32(smem);
    const int tid  = threadIdx.x;
    const int lane = tid & 31, wid = tid >> 5;
    const int g    = lane >> 2, t = lane & 3;
    const int wm   = wid & 3, wn = wid >> 2;       // 4m x 2n warp grid
    const int mbase = blockIdx.x * 128;
    const int split = blockIdx.z;
    const int koff  = split * klen;
    const int nch   = klen >> 5;

    // cp.async A mapping: 4 rows (crow+32j), 16B at ccol (linear 128B rows)
    const int crow = tid >> 3;
    const int ccol = (tid & 7) * 4;
    // cp.async W mapping: row = tid>>1, seg = tid&1 (2x16B each)
    const int wrow = tid >> 1;
    const int wseg = tid & 1;

    // ldmatrix lane address components (bytes, within buf)
    // A: matrix i fed by lanes 8i..8i+7: m0=[r0-7,klo] m1=[r8-15,klo] m2=[r0-7,khi] m3=[r8-15,khi]
    const uint32_t aoff_l = (uint32_t)(wm * 32 + ((lane >> 3) & 1) * 8 + (lane & 7)) * 80
                          + (uint32_t)((lane >> 4) * 4) * 4;
    // B: m0=[n(2j) rows, klo] m1=[n(2j), khi] m2=[n(2j+1), klo] m3=[n(2j+1), khi]
    const uint32_t boff_l = (uint32_t)(wn * 64 + ((lane >> 4) & 1) * 8 + (lane & 7)) * 80
                          + (uint32_t)(((lane >> 3) & 1) * 4) * 4;

    float acc[2][8][4];
#pragma unroll
    for (int i = 0; i < 2; i++)
#pragma unroll
        for (int j = 0; j < 8; j++)
#pragma unroll
            for (int q = 0; q < 4; q++) acc[i][j][q] = 0.f;

    auto issue = [&](int c) {
        // A f32 -> linear stage c%3 (row*32 + k layout)
        const uint32_t ba = sb + (uint32_t)(c % 3) * STG32B;
        const int k0 = koff + c * 32;
#pragma unroll
        for (int j = 0; j < 4; j++) {
            const int row = crow + j * 32;
            int gr = mbase + row; if (gr > M - 1) gr = M - 1;
            const int gk = k0 + ccol;
            const float* src = (gk < ksplit)
                ? (A1 + (size_t)gr * lda1 + gk)
                : (A2 + (size_t)gr * lda2 + (gk - ksplit));
            cp16(ba + (uint32_t)(row * 32 + ccol) * 4, src);
        }
        // W f16 -> bufW c%3 (64B data per row, 80B row stride)
        const uint32_t bw = sb + OFF_BUFW + (uint32_t)(c % 3) * 10240;
        const uint32_t* srcW = Wh + (size_t)wrow * (Ktot >> 1) + (k0 >> 1) + wseg * 8;
        cp16(bw + wrow * 80 + wseg * 32, srcW);
        cp16(bw + wrow * 80 + wseg * 32 + 16, srcW + 4);
        asm volatile("cp.async.commit_group;" ::: "memory");
    };

    issue(0);
    if (nch > 1) issue(1);

    for (int c = 0; c < nch; c++) {
        if (c + 1 < nch) asm volatile("cp.async.wait_group 1;" ::: "memory");
        else             asm volatile("cp.async.wait_group 0;" ::: "memory");
        __syncthreads();

        // ---- convert f32 stage (linear) -> fp16 bufA (80B-stride rows) ----
        {
            const float4* st4 = (const float4*)(smem + (c % 3) * STG32B);
            char* ba = smem + OFF_BUFA + (c % 2) * 10240;
#pragma unroll
            for (int q = 0; q < 4; q++) {
                const int idx = q * 256 + tid;          // float4 index, packed reads
                float4 v = st4[idx];
                const int row = idx >> 3;
                const int k04 = (idx & 7) * 4;          // starting k (float)
                uint2 h;
                h.x = f16x2(v.x, v.y);
                h.y = f16x2(v.z, v.w);
                *(uint2*)(ba + row * 80 + k04 * 2) = h;
            }
        }
        __syncthreads();
        if (c + 2 < nch) issue(c + 2);

        const uint32_t abase = sb + OFF_BUFA + (uint32_t)(c % 2) * 10240 + aoff_l;
        const uint32_t bbase = sb + OFF_BUFW + (uint32_t)(c % 3) * 10240 + boff_l;

#pragma unroll
        for (int s = 0; s < 2; s++) {
            uint32_t a[2][4];
            ldm4(a[0], abase + s * 32);              // mt=0: rows wm*32..+15
            ldm4(a[1], abase + 16 * 80 + s * 32);    // mt=1: rows +16..+31
            uint32_t b[8][2];
#pragma unroll
            for (int j = 0; j < 4; j++) {
                uint32_t r[4];
                ldm4(r, bbase + j * 16 * 80 + s * 32);
                b[2 * j][0] = r[0];  b[2 * j][1] = r[1];
                b[2 * j + 1][0] = r[2]; b[2 * j + 1][1] = r[3];
            }
#pragma unroll
            for (int mt = 0; mt < 2; mt++)
#pragma unroll
                for (int nt = 0; nt < 8; nt++)
                    mma16(acc[mt][nt], a[mt], b[nt]);
        }
    }

    // ---- epilogue ----
#pragma unroll
    for (int mt = 0; mt < 2; mt++) {
        const int row = mbase + wm * 32 + mt * 16 + g;
#pragma unroll
        for (int nt = 0; nt < 8; nt++) {
            const int col = wn * 64 + nt * 8 + 2 * t;
            if (Part) {
                float* dst = Part + ((size_t)split * M + row) * 128 + col;
                if (row < M)     *(float2*)(dst)           = make_float2(acc[mt][nt][0], acc[mt][nt][1]);
                if (row + 8 < M) *(float2*)(dst + 8 * 128) = make_float2(acc[mt][nt][2], acc[mt][nt][3]);
            } else {
                float b0 = bias[col], b1 = bias[col + 1];
                float v0 = acc[mt][nt][0] + b0, v1 = acc[mt][nt][1] + b1;
                float v2 = acc[mt][nt][2] + b0, v3 = acc[mt][nt][3] + b1;
                if (act == 1) {
                    v0 = fmaxf(v0, 0.f); v1 = fmaxf(v1, 0.f);
                    v2 = fmaxf(v2, 0.f); v3 = fmaxf(v3, 0.f);
                } else {
                    v0 = eluf(v0); v1 = eluf(v1); v2 = eluf(v2); v3 = eluf(v3);
                }
                if (row < M)     *(float2*)(C + (size_t)row * ldc + col)       = make_float2(v0, v1);
                if (row + 8 < M) *(float2*)(C + (size_t)(row + 8) * ldc + col) = make_float2(v2, v3);
            }
        }
    }
}

// ---------------- combine K-split partials: dst = act(sum + bias) -------------
__global__ void combine_kernel(int nsplit, int total4, const float* __restrict__ bias,
                               float* __restrict__ dst, int act, int stride4)
{
    int i = blockIdx.x * blockDim.x + threadIdx.x;
    if (i >= total4) return;
    const float4* p = (const float4*)g_part;
    float4 v = p[i];
    for (int s = 1; s < nsplit; s++) {
        float4 w = p[i + s * stride4];
        v.x += w.x; v.y += w.y; v.z += w.z; v.w += w.w;
    }
    const int col = (i * 4) & 127;   // ldc = 128
    v.x += bias[col]; v.y += bias[col + 1]; v.z += bias[col + 2]; v.w += bias[col + 3];
    if (act == 1) {
        v.x = fmaxf(v.x, 0.f); v.y = fmaxf(v.y, 0.f); v.z = fmaxf(v.z, 0.f); v.w = fmaxf(v.w, 0.f);
    } else {
        v.x = eluf(v.x); v.y = eluf(v.y); v.z = eluf(v.z); v.w = eluf(v.w);
    }
    ((float4*)dst)[i] = v;
}

// ---------------- GEMM v2 (exact fp32 accum, f32x2) — used for g1 --------------
#define BM 64
#define BN 128
#define BK 16
#define ASTRIDE 68

__global__ __launch_bounds__(128, 3) void gemm2_kernel(
    const float* __restrict__ A1, int lda1, int ksplit,
    const float* __restrict__ A2, int lda2,
    const float* __restrict__ W, int ldw,
    const float* __restrict__ bias,
    float* __restrict__ C, int ldc,
    int M, int klen, int act, int out_half)
{
    __shared__ float As[BK][ASTRIDE];
    __shared__ float Bs[BK][BN];
    const int tid    = threadIdx.x;
    const int brow   = blockIdx.x * BM;
    const int colOff = blockIdx.y * BN;

    const int tr = tid >> 4;
    const int tc = tid & 15;

    ull acc[8][4];
#pragma unroll
    for (int i = 0; i < 8; i++)
#pragma unroll
        for (int j = 0; j < 4; j++) acc[i][j] = 0ULL;

    const int ar0 = tid >> 2;
    const int ac4 = (tid & 3) * 4;
    const int bq  = (tid & 31) * 4;
    const int br0 = tid >> 5;

    for (int k0 = 0; k0 < klen; k0 += BK) {
#pragma unroll
        for (int h = 0; h < 2; h++) {
            const int row = ar0 + h * 32;
            const int gr  = brow + row;
            const int gk  = k0 + ac4;
            float4 v = make_float4(0.f, 0.f, 0.f, 0.f);
            if (gr < M) {
                const float* p = (gk < ksplit)
                    ? (A1 + (size_t)gr * lda1 + gk)
                    : (A2 + (size_t)gr * lda2 + (gk - ksplit));
                v = *(const float4*)p;
            }
            As[ac4 + 0][row] = v.x;
            As[ac4 + 1][row] = v.y;
            As[ac4 + 2][row] = v.z;
            As[ac4 + 3][row] = v.w;
        }
#pragma unroll
        for (int j = 0; j < 4; j++) {
            const int row = br0 + j * 4;
            const float4 v = *(const float4*)(W + (size_t)(k0 + row) * ldw
                                              + colOff + bq);
            *(float4*)&Bs[row][bq] = v;
        }
        __syncthreads();

#pragma unroll
        for (int kk = 0; kk < BK; kk++) {
            float a[8];
            *(float4*)(a)     = *(const float4*)&As[kk][tr * 8];
            *(float4*)(a + 4) = *(const float4*)&As[kk][tr * 8 + 4];
            ulonglong2 bA = *(const ulonglong2*)&Bs[kk][tc * 4];
            ulonglong2 bB = *(const ulonglong2*)&Bs[kk][64 + tc * 4];
#pragma unroll
            for (int i = 0; i < 8; i++) {
                ull av = bcast2(a[i]);
                fma2(acc[i][0], av, bA.x);
                fma2(acc[i][1], av, bA.y);
                fma2(acc[i][2], av, bB.x);
                fma2(acc[i][3], av, bB.y);
            }
        }
        __syncthreads();
    }

#pragma unroll
    for (int i = 0; i < 8; i++) {
        const int gr = brow + tr * 8 + i;
        if (gr >= M) continue;
        float2 p0 = unpack2(acc[i][0]), p1 = unpack2(acc[i][1]);
        float2 p2 = unpack2(acc[i][2]), p3 = unpack2(acc[i][3]);
        float4 v0 = make_float4(p0.x, p0.y, p1.x, p1.y);
        float4 v1 = make_float4(p2.x, p2.y, p3.x, p3.y);
        const int c0 = colOff + tc * 4;
        const int c1 = colOff + 64 + tc * 4;
        if (bias) {
            v0.x += bias[c0]; v0.y += bias[c0 + 1]; v0.z += bias[c0 + 2]; v0.w += bias[c0 + 3];
            v1.x += bias[c1]; v1.y += bias[c1 + 1]; v1.z += bias[c1 + 2]; v1.w += bias[c1 + 3];
        }
        if (act == 1) {
            v0.x = fmaxf(v0.x, 0.f); v0.y = fmaxf(v0.y, 0.f); v0.z = fmaxf(v0.z, 0.f); v0.w = fmaxf(v0.w, 0.f);
            v1.x = fmaxf(v1.x, 0.f); v1.y = fmaxf(v1.y, 0.f); v1.z = fmaxf(v1.z, 0.f); v1.w = fmaxf(v1.w, 0.f);
        } else if (act == 2) {
            v0.x = eluf(v0.x); v0.y = eluf(v0.y); v0.z = eluf(v0.z); v0.w = eluf(v0.w);
            v1.x = eluf(v1.x); v1.y = eluf(v1.y); v1.z = eluf(v1.z); v1.w = eluf(v1.w);
        }
        if (out_half) {
            __half* dst = (__half*)C + (size_t)gr * ldc;
            uint2 h0, h1;
            h0.x = f16x2(v0.x, v0.y); h0.y = f16x2(v0.z, v0.w);
            h1.x = f16x2(v1.x, v1.y); h1.y = f16x2(v1.z, v1.w);
            *(uint2*)(dst + c0) = h0;
            *(uint2*)(dst + c1) = h1;
        } else {
            float* dst = C + (size_t)gr * ldc;
            *(float4*)(dst + c0) = v0;
            *(float4*)(dst + c1) = v1;
        }
    }
}

// ---------------- CSR build ---------------------------------------------------
__global__ void init_deg_kernel(int n)
{
    int i = blockIdx.x * blockDim.x + threadIdx.x;
    if (i < n) g_deg[i] = 0;
}

__global__ void hist_kernel(const int* __restrict__ ei, int E, int Etot)
{
    int e = blockIdx.x * blockDim.x + threadIdx.x;
    if (e >= Etot) return;
    int dst = (e < E) ? ei[E + e] : (e - E);
    atomicAdd(&g_deg[dst], 1);
}

__global__ __launch_bounds__(1024) void scan_kernel(int n)
{
    __shared__ int sb[1024];
    const int tid = threadIdx.x;
    const int CH  = (NN + 1023) / 1024;   // 20
    int local[CH];
    int base = tid * CH;
    int sum = 0;
#pragma unroll
    for (int j = 0; j < CH; j++) {
        int idx = base + j;
        int v = (idx < n) ? g_deg[idx] : 0;
        local[j] = v;
        sum += v;
    }
    sb[tid] = sum;
    __syncthreads();
    for (int off = 1; off < 1024; off <<= 1) {
        int v = (tid >= off) ? sb[tid - off] : 0;
        __syncthreads();
        sb[tid] += v;
        __syncthreads();
    }
    int run = sb[tid] - sum;
#pragma unroll
    for (int j = 0; j < CH; j++) {
        int idx = base + j;
        if (idx < n) {
            g_rowptr[idx] = run;
            g_cursor[idx] = run;
            run += local[j];
        }
    }
    if (tid == 1023) g_rowptr[n] = sb[1023];
}

__global__ void scatter_kernel(const int* __restrict__ ei, int E, int Etot)
{
    int e = blockIdx.x * blockDim.x + threadIdx.x;
    if (e >= Etot) return;
    int src, dst;
    if (e < E) { src = ei[e]; dst = ei[E + e]; }
    else       { src = e - E; dst = e - E; }
    int pos = atomicAdd(&g_cursor[dst], 1);
    g_csr[pos] = src;
}

// ---------------- GAT1 attention coefficients (h1 in fp16) --------------------
__global__ __launch_bounds__(256) void att1_kernel(
    const float* __restrict__ g1_as, const float* __restrict__ g1_ad, int n)
{
    int p = blockIdx.x * 8 + (threadIdx.x >> 5);
    int lane = threadIdx.x & 31;
    if (p >= n * 2) return;
    int node = p >> 1, h = p & 1;
    uint2 r = *(const uint2*)(g_h1h + (size_t)node * 256 + h * 128 + lane * 4);
    float2 f0 = __half22float2(*(__half2*)&r.x);
    float2 f1 = __half22float2(*(__half2*)&r.y);
    float4 as = *(const float4*)(g1_as + h * 128 + lane * 4);
    float4 ad = *(const float4*)(g1_ad + h * 128 + lane * 4);
    float vs = f0.x * as.x + f0.y * as.y + f1.x * as.z + f1.y * as.w;
    float vd = f0.x * ad.x + f0.y * ad.y + f1.x * ad.z + f1.y * ad.w;
#pragma unroll
    for (int o = 16; o; o >>= 1) {
        vs += __shfl_xor_sync(0xffffffffu, vs, o);
        vd += __shfl_xor_sync(0xffffffffu, vd, o);
    }
    if (lane == 0) { g_as1[p] = vs; g_ad1[p] = vd; }
}

// ---------------- GAT1 aggregate (atomic-free via CSR, fp16 values) ------------
__global__ __launch_bounds__(256) void gat1_kernel(const float* __restrict__ g1_b, int n)
{
    int p = blockIdx.x * 8 + (threadIdx.x >> 5);
    int lane = threadIdx.x & 31;
    if (p >= n * 2) return;
    int node = p >> 1, h = p & 1;
    int beg = g_rowptr[node], end = g_rowptr[node + 1];
    float adv = g_ad1[node * 2 + h];

    float m = -1e30f;
    for (int i = beg + lane; i < end; i += 32) {
        int s = g_csr[i];
        m = fmaxf(m, lrelu(g_as1[s * 2 + h] + adv));
    }
#pragma unroll
    for (int o = 16; o; o >>= 1) m = fmaxf(m, __shfl_xor_sync(0xffffffffu, m, o));

    float ssum = 0.f, ax = 0.f, ay = 0.f, az = 0.f, aw = 0.f;
    const __half* hb = g_h1h + h * 128 + lane * 4;
    for (int i = beg; i < end; ++i) {
        int s = g_csr[i];                                // broadcast load
        float w = expf(lrelu(g_as1[s * 2 + h] + adv) - m);
        ssum += w;
        uint2 r = *(const uint2*)(hb + (size_t)s * 256);
        float2 f0 = __half22float2(*(__half2*)&r.x);
        float2 f1 = __half22float2(*(__half2*)&r.y);
        ax = fmaf(w, f0.x, ax); ay = fmaf(w, f0.y, ay);
        az = fmaf(w, f1.x, az); aw = fmaf(w, f1.y, aw);
    }
    float inv = 1.f / (ssum + 1e-16f);
    int col = h * 128 + lane * 4;
    float4 o;
    o.x = eluf(ax * inv + g1_b[col + 0]);
    o.y = eluf(ay * inv + g1_b[col + 1]);
    o.z = eluf(az * inv + g1_b[col + 2]);
    o.w = eluf(aw * inv + g1_b[col + 3]);
    *(float4*)(g_x1 + (size_t)node * 256 + col) = o;
}

// ---------------- GAT2 projection + attention coefficients --------------------
__global__ __launch_bounds__(256) void h2_kernel(
    const float* __restrict__ g2_W, const float* __restrict__ g2_as,
    const float* __restrict__ g2_ad, int n)
{
    __shared__ float4 sW[256];
    __shared__ float4 s_as, s_ad;
    const int tid = threadIdx.x;
    sW[tid] = *(const float4*)(g2_W + tid * 4);
    if (tid == 0) { s_as = *(const float4*)g2_as; s_ad = *(const float4*)g2_ad; }
    __syncthreads();
    int node = blockIdx.x * 8 + (tid >> 5);
    int lane = tid & 31;
    if (node >= n) return;
    float a0 = 0.f, a1 = 0.f, a2 = 0.f, a3 = 0.f;
    const float* xr = g_x1 + (size_t)node * 256;
    for (int k = lane; k < 256; k += 32) {
        float x = xr[k];
        float4 w = sW[k];
        a0 = fmaf(x, w.x, a0); a1 = fmaf(x, w.y, a1);
        a2 = fmaf(x, w.z, a2); a3 = fmaf(x, w.w, a3);
    }
#pragma unroll
    for (int o = 16; o; o >>= 1) {
        a0 += __shfl_xor_sync(0xffffffffu, a0, o);
        a1 += __shfl_xor_sync(0xffffffffu, a1, o);
        a2 += __shfl_xor_sync(0xffffffffu, a2, o);
        a3 += __shfl_xor_sync(0xffffffffu, a3, o);
    }
    if (lane == 0) {
        *(float4*)(g_h2 + (size_t)node * 4) = make_float4(a0, a1, a2, a3);
        g_as2[node] = a0 * s_as.x + a1 * s_as.y + a2 * s_as.z + a3 * s_as.w;
        g_ad2[node] = a0 * s_ad.x + a1 * s_ad.y + a2 * s_ad.z + a3 * s_ad.w;
    }
}

// ---------------- GAT2 aggregate -> final output ------------------------------
__global__ __launch_bounds__(256) void gat2_kernel(
    const float* __restrict__ g2_b, float* __restrict__ out, int n)
{
    int node = blockIdx.x * 8 + (threadIdx.x >> 5);
    int lane = threadIdx.x & 31;
    if (node >= n) return;
    int beg = g_rowptr[node], end = g_rowptr[node + 1];
    float adv = g_ad2[node];

    float m = -1e30f;
    for (int i = beg + lane; i < end; i += 32) {
        int s = g_csr[i];
        m = fmaxf(m, lrelu(g_as2[s] + adv));
    }
#pragma unroll
    for (int o = 16; o; o >>= 1) m = fmaxf(m, __shfl_xor_sync(0xffffffffu, m, o));

    float ssum = 0.f, a0 = 0.f, a1 = 0.f, a2 = 0.f, a3 = 0.f;
    for (int i = beg + lane; i < end; i += 32) {
        int s = g_csr[i];
        float w = expf(lrelu(g_as2[s] + adv) - m);
        ssum += w;
        float4 hv = *(const float4*)(g_h2 + (size_t)s * 4);
        a0 = fmaf(w, hv.x, a0); a1 = fmaf(w, hv.y, a1);
        a2 = fmaf(w, hv.z, a2); a3 = fmaf(w, hv.w, a3);
    }
#pragma unroll
    for (int o = 16; o; o >>= 1) {
        ssum += __shfl_xor_sync(0xffffffffu, ssum, o);
        a0 += __shfl_xor_sync(0xffffffffu, a0, o);
        a1 += __shfl_xor_sync(0xffffffffu, a1, o);
        a2 += __shfl_xor_sync(0xffffffffu, a2, o);
        a3 += __shfl_xor_sync(0xffffffffu, a3, o);
    }
    if (lane == 0) {
        float inv = 1.f / (ssum + 1e-16f);
        float4 o4 = make_float4(a0 * inv + g2_b[0], a1 * inv + g2_b[1],
                                a2 * inv + g2_b[2], a3 * inv + g2_b[3]);
        *(float4*)(out + (size_t)node * 4) = o4;
    }
}

// ---------------- launch -------------------------------------------------------
extern "C" void kernel_launch(void* const* d_in, const int* in_sizes, int n_in,
                              void* d_out, int out_size)
{
    (void)n_in; (void)out_size;
    const float* text     = (const float*)d_in[0];
    const float* mel      = (const float*)d_in[1];
    const int*   ei       = (const int*)  d_in[2];
    const float* mel_W    = (const float*)d_in[3];
    const float* mel_b    = (const float*)d_in[4];
    const float* concat_W = (const float*)d_in[5];
    const float* concat_b = (const float*)d_in[6];
    const float* g1_W     = (const float*)d_in[7];
    const float* g1_as    = (const float*)d_in[8];
    const float* g1_ad    = (const float*)d_in[9];
    const float* g1_b     = (const float*)d_in[10];
    const float* g2_W     = (const float*)d_in[11];
    const float* g2_as    = (const float*)d_in[12];
    const float* g2_ad    = (const float*)d_in[13];
    const float* g2_b     = (const float*)d_in[14];
    float* out = (float*)d_out;

    const int n    = in_sizes[0] / TXT;       // 20000
    const int E    = in_sizes[2] / 2;         // 640000
    const int Etot = E + n;                   // 660000

    float *p_melf, *p_x0, *p_part;
    __half* p_h1h;
    uint32_t *p_Wh, *p_Whc;
    cudaGetSymbolAddress((void**)&p_melf, g_melf);
    cudaGetSymbolAddress((void**)&p_x0,   g_x0);
    cudaGetSymbolAddress((void**)&p_part, g_part);
    cudaGetSymbolAddress((void**)&p_h1h,  g_h1h);
    cudaGetSymbolAddress((void**)&p_Wh,   g_Wh);
    cudaGetSymbolAddress((void**)&p_Whc,  g_Whc);

    cudaFuncSetAttribute(mmagemm_h,
                         cudaFuncAttributeMaxDynamicSharedMemorySize, HSMEM);

    // side stream + events for CSR overlap (created once; reused in capture)
    static cudaStream_t s_side = nullptr;
    static cudaEvent_t  ev_fork = nullptr, ev_join = nullptr;
    if (!s_side) {
        cudaStreamCreateWithFlags(&s_side, cudaStreamNonBlocking);
        cudaEventCreateWithFlags(&ev_fork, cudaEventDisableTiming);
        cudaEventCreateWithFlags(&ev_join, cudaEventDisableTiming);
    }

    const int tiles128 = (n + 127) / 128;     // 157
    const int mblocks  = (n + BM - 1) / BM;   // 313
    const int total4   = n * HID / 4;
    const int stride4  = n * HID / 4;

    // main #1: W prep for mel
    wprep_h<<<(HID * MELK / 2 + 255) / 256, 256>>>(mel_W, p_Wh, MELK);

    // fork side stream: CSR build runs concurrently with the GEMM pipeline
    cudaEventRecord(ev_fork, 0);
    cudaStreamWaitEvent(s_side, ev_fork, 0);
    init_deg_kernel<<<(n + 255) / 256, 256, 0, s_side>>>(n);
    hist_kernel<<<(Etot + 255) / 256, 256, 0, s_side>>>(ei, E, Etot);

    // mel_feat = relu(mel @ mel_W + mel_b): v5 ldmatrix, 4-way K-split
    mmagemm_h<<<dim3(tiles128, 1, 4), 256, HSMEM>>>(
        mel, MELK, MELK, mel, MELK, p_Wh, nullptr,
        nullptr, HID, p_part, n, MELK, MELK / 4, 0);
    combine_kernel<<<(total4 + 255) / 256, 256>>>(4, total4, mel_b, p_melf, 1, stride4);

    scan_kernel<<<1, 1024, 0, s_side>>>(n);
    scatter_kernel<<<(Etot + 255) / 256, 256, 0, s_side>>>(ei, E, Etot);
    cudaEventRecord(ev_join, s_side);

    // x0 = elu([text | mel_feat] @ concat_W + concat_b): v5 ldmatrix, 2-way K-split
    wprep_h<<<(HID * (TXT + HID) / 2 + 255) / 256, 256>>>(concat_W, p_Whc, TXT + HID);
    mmagemm_h<<<dim3(tiles128, 1, 2), 256, HSMEM>>>(
        text, TXT, TXT, p_melf, HID, p_Whc, nullptr,
        nullptr, HID, p_part, n, TXT + HID, (TXT + HID) / 2, 0);
    combine_kernel<<<(total4 + 255) / 256, 256>>>(2, total4, concat_b, p_x0, 2, stride4);

    // h1 = x0 @ g1_W (fp32 accum, fp16 storage)
    gemm2_kernel<<<dim3(mblocks, 2), 128>>>(p_x0, HID, HID, p_x0, HID,
                                            g1_W, 256, nullptr,
                                            (float*)p_h1h, 256, n, HID, 0, 1);

    att1_kernel<<<(2 * n + 7) / 8, 256>>>(g1_as, g1_ad, n);

    // join: gat1 needs the CSR
    cudaStreamWaitEvent(0, ev_join, 0);
    gat1_kernel<<<(2 * n + 7) / 8, 256>>>(g1_b, n);
    h2_kernel<<<(n + 7) / 8, 256>>>(g2_W, g2_as, g2_ad, n);
    gat2_kernel<<<(n + 7) / 8, 256>>>(g2_b, out, n);
}